// round 13
// baseline (speedup 1.0000x reference)
#include <cuda_runtime.h>
#include <math.h>
#include <stdint.h>

#define ATT_SCALE 0.08838834764831845f   // 128^-0.5
#define PW 36                            // u32-word pitch of bf16 tiles (4 mod 32 -> conflict-free)

#define TILE_W  (128*PW)                 // 4608 words per 128-row tile
#define TILEQ_W (192*PW)                 // 6912 words per 192-row tile
#define SMEM_SZ 73728                    // pk/attn: 4 x 128-row tiles
#define SMEM_Q  101376                   // qproj: tiles (92160) / 192x132 fp32 stage

// ----------------- scratch (device globals; only referenced from device code) -----------------
// q/k/vT cached directly as preconverted hi/lo bf16 word tiles: [slice][chunk][TILE_W]
__device__ __align__(128) unsigned g_qth[512*2*TILE_W];   // q: scale+bias baked in
__device__ __align__(128) unsigned g_qtl[512*2*TILE_W];
__device__ __align__(128) unsigned g_kth[512*2*TILE_W];
__device__ __align__(128) unsigned g_ktl[512*2*TILE_W];
__device__ __align__(128) unsigned g_vth[512*2*TILE_W];   // vT (rows=w, k-cols=h)
__device__ __align__(128) unsigned g_vtl[512*2*TILE_W];
__device__ __align__(128) float g_xs [65536*128];         // (B,H,W,C) sampled
__device__ __align__(128) float g_z  [4*64*16384];        // 50 offset-tap projections per batch
__device__ __align__(128) float g_coords[65536*2];
__device__ __align__(128) float g_Weff[50*128];
__device__ __align__(128) float g_zbias[50];
__device__ __align__(128) float g_beff[2];
__device__ __align__(128) float g_Wqz[192*128];
__device__ __align__(128) unsigned g_WthQ[2][TILEQ_W];
__device__ __align__(128) unsigned g_WtlQ[2][TILEQ_W];
__device__ __align__(128) unsigned g_Wth[3][2][TILE_W];   // 0=Wk, 1=Wv, 2=Wo
__device__ __align__(128) unsigned g_Wtl[3][2][TILE_W];

// ----------------- helpers -----------------
static __device__ __forceinline__ void mmabf(float c[4], const unsigned a[4],
                                             unsigned b0, unsigned b1) {
    asm volatile("mma.sync.aligned.m16n8k16.row.col.f32.bf16.bf16.f32 "
        "{%0,%1,%2,%3},{%4,%5,%6,%7},{%8,%9},{%0,%1,%2,%3};"
        : "+f"(c[0]), "+f"(c[1]), "+f"(c[2]), "+f"(c[3])
        : "r"(a[0]), "r"(a[1]), "r"(a[2]), "r"(a[3]), "r"(b0), "r"(b1));
}
static __device__ __forceinline__ void ldsm4(unsigned r[4], unsigned addr) {
    asm volatile("ldmatrix.sync.aligned.m8n8.x4.shared.b16 {%0,%1,%2,%3},[%4];"
        : "=r"(r[0]), "=r"(r[1]), "=r"(r[2]), "=r"(r[3]) : "r"(addr));
}
static __device__ __forceinline__ unsigned packh(float x0, float x1) {
    unsigned h; asm("cvt.rn.bf16x2.f32 %0,%1,%2;" : "=r"(h) : "f"(x1), "f"(x0)); return h;
}
static __device__ __forceinline__ unsigned packl(float x0, float x1, unsigned h) {
    float h0 = __uint_as_float(h << 16), h1 = __uint_as_float(h & 0xffff0000u);
    return packh(x0 - h0, x1 - h1);
}

// load a ROWSx64 fp32 chunk (cols kc*64..) into hi/lo bf16-pair word tiles; 256 threads
template<int ROWS>
static __device__ __forceinline__ void fill_chunkR(const float* __restrict__ src, int ld, int kc,
                                                   float scale, unsigned* th, unsigned* tl, int tid) {
#pragma unroll
    for (int it = 0; it < ROWS/16; it++) {
        int idx = it*256 + tid;
        int r = idx >> 4, c4 = (idx & 15)*4;
        float4 v = *(const float4*)(src + (size_t)r*ld + kc*64 + c4);
        float x0 = v.x*scale, x1 = v.y*scale, x2 = v.z*scale, x3 = v.w*scale;
        unsigned h0 = packh(x0, x1), h1 = packh(x2, x3);
        unsigned l0 = packl(x0, x1, h0), l1 = packl(x2, x3, h1);
        int o = r*PW + (c4 >> 1);
        th[o] = h0; th[o+1] = h1;
        tl[o] = l0; tl[o+1] = l1;
    }
}

// copy a preconverted NW-word tile pair (global -> smem); 256 threads
template<int NW>
static __device__ __forceinline__ void copy_tileN(const unsigned* __restrict__ gh,
                                                  const unsigned* __restrict__ gl,
                                                  unsigned* th, unsigned* tl, int tid) {
#pragma unroll
    for (int it = 0; it < (NW/4 + 255)/256; it++) {
        int idx = it*256 + tid;
        if (idx < NW/4) {
            ((uint4*)th)[idx] = ((const uint4*)gh)[idx];
            ((uint4*)tl)[idx] = ((const uint4*)gl)[idx];
        }
    }
}

// warp GEMM over one K=64 chunk via ldmatrix: C[m0..+MT*16][n0..+NT*8] += A @ B^T (bf16x3)
template<int MT, int NT>
static __device__ __forceinline__ void wgemm(unsigned AhB, unsigned AlB,
                                             unsigned BhB, unsigned BlB,
                                             int m0, int n0, int lane, float (*acc)[4]) {
    unsigned aoff = ((m0 + ((lane>>3)&1)*8 + (lane&7))*PW + ((lane>>4)<<2))*4;
    unsigned boff = ((n0 + (lane>>4)*8 + (lane&7))*PW + (((lane>>3)&1)<<2))*4;
#pragma unroll
    for (int ks = 0; ks < 4; ks++) {
        unsigned ka = ks*32;
        unsigned ah[MT][4], al[MT][4];
#pragma unroll
        for (int mt = 0; mt < MT; mt++) {
            ldsm4(ah[mt], AhB + aoff + mt*(16*PW*4) + ka);
            ldsm4(al[mt], AlB + aoff + mt*(16*PW*4) + ka);
        }
#pragma unroll
        for (int ntp = 0; ntp < NT/2; ntp++) {
            unsigned bh[4], bl[4];
            unsigned bo = boff + ntp*(16*PW*4) + ka;
            ldsm4(bh, BhB + bo);
            ldsm4(bl, BlB + bo);
#pragma unroll
            for (int mt = 0; mt < MT; mt++) {
                float* c0 = acc[mt*NT + 2*ntp];
                float* c1 = acc[mt*NT + 2*ntp + 1];
                mmabf(c0, ah[mt], bh[0], bh[1]);
                mmabf(c0, ah[mt], bl[0], bl[1]);
                mmabf(c0, al[mt], bh[0], bh[1]);
                mmabf(c1, ah[mt], bh[2], bh[3]);
                mmabf(c1, ah[mt], bl[2], bl[3]);
                mmabf(c1, al[mt], bh[2], bh[3]);
            }
        }
    }
}

// ----------------- prep: Weff fold, Wq copy, zero pad, beff -----------------
__global__ void prep_kernel(const float* __restrict__ Wq, const float* __restrict__ Wc1,
                            const float* __restrict__ Wc2, const float* __restrict__ bc1) {
    int blk = blockIdx.x, tid = threadIdx.x;
    if (blk < 50) {
        int j = blk / 25, t = blk % 25;
        if (tid < 128) {
            float s = 0.f;
            for (int o = 0; o < 128; o++)
                s += Wc2[j*128 + o] * Wc1[((size_t)(o*128 + tid))*25 + t];
            g_Weff[blk*128 + tid] = s;
        }
    } else {
        for (int i = tid; i < 16384; i += 256) g_Wqz[i] = Wq[i];
        for (int i = tid; i < 14*128; i += 256) g_Wqz[178*128 + i] = 0.f;
        if (tid < 2) {
            float s = 0.f;
            for (int o = 0; o < 128; o++) s += Wc2[tid*128 + o] * bc1[o];
            g_beff[tid] = s;
        }
    }
}

// ----------------- prep2: Wz = Weff @ Wq ; zbias = Weff @ bq -----------------
__global__ void prep2_kernel(const float* __restrict__ Wq, const float* __restrict__ bq) {
    int jt = blockIdx.x, tid = threadIdx.x;
    float s = 0.f;
    for (int c = 0; c < 128; c++) s += g_Weff[jt*128 + c] * Wq[c*128 + tid];
    g_Wqz[(128 + jt)*128 + tid] = s;
    if (tid == 0) {
        float z = 0.f;
        for (int c = 0; c < 128; c++) z += g_Weff[jt*128 + c] * bq[c];
        g_zbias[jt] = z;
    }
}

// ----------------- prepW: convert weights to hi/lo word tiles -----------------
__global__ void prepW_kernel(const float* __restrict__ Wk, const float* __restrict__ Wv,
                             const float* __restrict__ Wo) {
    int blk = blockIdx.x, tid = threadIdx.x;    // 8 blocks
    if (blk < 2) {
        fill_chunkR<192>(g_Wqz, 128, blk, 1.f, g_WthQ[blk], g_WtlQ[blk], tid);
    } else {
        int w = (blk - 2) >> 1, kc = (blk - 2) & 1;
        const float* W = (w == 0) ? Wk : (w == 1) ? Wv : Wo;
        fill_chunkR<128>(W, 128, kc, 1.f, g_Wth[w][kc], g_Wtl[w][kc], tid);
    }
}

// ----------------- qproj: [q | z] = x_slice @ [Wq;Wz]^T, N=192 -----------------
__global__ void __launch_bounds__(256) qproj_kernel(const float* __restrict__ x,
                                                    const float* __restrict__ bq) {
    extern __shared__ unsigned smw[];
    unsigned *Ah = smw, *Al = smw + TILE_W, *Bh = smw + 2*TILE_W, *Bl = smw + 2*TILE_W + TILEQ_W;
    unsigned sb = (unsigned)__cvta_generic_to_shared(smw);
    unsigned AhB = sb, AlB = sb + TILE_W*4, BhB = sb + 2*TILE_W*4, BlB = sb + (2*TILE_W + TILEQ_W)*4;
    int tid = threadIdx.x, wid = tid >> 5, lane = tid & 31;
    int g = lane >> 2, tg = lane & 3;
    int b = blockIdx.x >> 7, h = blockIdx.x & 127;
    const float* src = x + (size_t)b*2097152 + (size_t)h*16384;

    float acc[24][4] = {};
    int m0 = (wid >> 1)*32, n0 = (wid & 1)*96;
    for (int kc = 0; kc < 2; kc++) {
        fill_chunkR<128>(src, 128, kc, 1.f, Ah, Al, tid);
        copy_tileN<TILEQ_W>(g_WthQ[kc], g_WtlQ[kc], Bh, Bl, tid);
        __syncthreads();
        wgemm<2,12>(AhB, AlB, BhB, BlB, m0, n0, lane, acc);
        __syncthreads();
    }

    // stage transposed [n][m], pitch 132, 192 rows
    float* stage = (float*)smw;
#pragma unroll
    for (int mt = 0; mt < 2; mt++)
#pragma unroll
        for (int nt = 0; nt < 12; nt++) {
            int m = m0 + mt*16 + g, n = n0 + nt*8 + 2*tg;
            stage[n*132 + m]         = acc[mt*12+nt][0];
            stage[(n+1)*132 + m]     = acc[mt*12+nt][1];
            stage[n*132 + m + 8]     = acc[mt*12+nt][2];
            stage[(n+1)*132 + m + 8] = acc[mt*12+nt][3];
        }
    __syncthreads();

    // q out -> bf16 hi/lo chunk tiles (row h), ATT_SCALE and bias baked in
#pragma unroll
    for (int it = 0; it < 32; it++) {
        int idx = it*256 + tid;              // 8192 words
        int c = idx >> 6, r = idx & 63;
        int kc = r >> 5, j = r & 31;
        float bias = bq[c];
        float v0 = (stage[c*132 + kc*64 + 2*j]     + bias)*ATT_SCALE;
        float v1 = (stage[c*132 + kc*64 + 2*j + 1] + bias)*ATT_SCALE;
        unsigned hw = packh(v0, v1);
        size_t o = (size_t)((b*128 + c)*2 + kc)*TILE_W + h*PW + j;
        g_qth[o] = hw;
        g_qtl[o] = packl(v0, v1, hw);
    }
    // z out: (b, jt, h, w), raw fp32
    float* zd = g_z + (size_t)b*1048576 + (size_t)h*128;
#pragma unroll
    for (int it = 0; it < 7; it++) {
        int idx = it*256 + tid;
        if (idx < 1600) {
            int zr = idx >> 5, m4 = (idx & 31)*4;
            float4 v = *(float4*)(stage + (128 + zr)*132 + m4);
            *(float4*)(zd + (size_t)zr*16384 + m4) = v;
        }
    }
}

// ----------------- offset2: 25-tap shifted sum over z + coords -----------------
__global__ void __launch_bounds__(256) offset2_kernel() {
    int p = blockIdx.x*256 + threadIdx.x;
    int b = p >> 14, rem = p & 16383;
    int h = rem >> 7, w = rem & 127;
    const float* zb = g_z + (size_t)b*1048576;
    float a0 = g_beff[0], a1 = g_beff[1];
#pragma unroll
    for (int kh = 0; kh < 5; kh++) {
        int hh = h + kh - 2;
        if ((unsigned)hh > 127u) continue;
#pragma unroll
        for (int kw = 0; kw < 5; kw++) {
            int ww = w + kw - 2;
            if ((unsigned)ww > 127u) continue;
            int t = kh*5 + kw, sp = hh*128 + ww;
            a0 += zb[(size_t)t*16384 + sp]        + g_zbias[t];
            a1 += zb[(size_t)(25 + t)*16384 + sp] + g_zbias[25 + t];
        }
    }
    float off0 = tanhf(a0)*5.f, off1 = tanhf(a1)*5.f;
    g_coords[2*p]     = ((float)w + off0)*(128.f/127.f) - 0.5f;
    g_coords[2*p + 1] = ((float)h + off1)*(128.f/127.f) - 0.5f;
}

// ----------------- k / vT projection (N=128), bf16-tile epilogue -----------------
__global__ void __launch_bounds__(256) pk_kernel(int blk_mul, int row_mul,
                                                 int wsel, int dst_sel,
                                                 const float* __restrict__ bias,
                                                 const float* __restrict__ rel) {
    extern __shared__ unsigned smw[];
    unsigned *Ah = smw, *Al = smw + TILE_W, *Bh = smw + 2*TILE_W, *Bl = smw + 3*TILE_W;
    unsigned sb = (unsigned)__cvta_generic_to_shared(smw);
    int tid = threadIdx.x, wid = tid >> 5, lane = tid & 31;
    int g = lane >> 2, tg = lane & 3;
    int b = blockIdx.x >> 7, q2 = blockIdx.x & 127;
    const float* src = g_xs + (size_t)b*2097152 + (size_t)q2*blk_mul;
    unsigned* dth = dst_sel ? g_vth : g_kth;
    unsigned* dtl = dst_sel ? g_vtl : g_ktl;

    float acc[16][4] = {};
    int m0 = (wid >> 1)*32, n0 = (wid & 1)*64;
    for (int kc = 0; kc < 2; kc++) {
        fill_chunkR<128>(src, row_mul, kc, 1.f, Ah, Al, tid);
        copy_tileN<TILE_W>(g_Wth[wsel][kc], g_Wtl[wsel][kc], Bh, Bl, tid);
        __syncthreads();
        wgemm<2,8>(sb, sb + TILE_W*4, sb + 2*TILE_W*4, sb + 3*TILE_W*4, m0, n0, lane, acc);
        __syncthreads();
    }

    float* stage = (float*)smw;
#pragma unroll
    for (int mt = 0; mt < 2; mt++)
#pragma unroll
        for (int nt = 0; nt < 8; nt++) {
            int m = m0 + mt*16 + g, n = n0 + nt*8 + 2*tg;
            stage[n*132 + m]         = acc[mt*8+nt][0];
            stage[(n+1)*132 + m]     = acc[mt*8+nt][1];
            stage[n*132 + m + 8]     = acc[mt*8+nt][2];
            stage[(n+1)*132 + m + 8] = acc[mt*8+nt][3];
        }
    __syncthreads();

    // epilogue: bf16 hi/lo tile row q2 per slice (b,c)
#pragma unroll
    for (int it = 0; it < 32; it++) {
        int idx = it*256 + tid;              // 8192 words
        int c = idx >> 6, r = idx & 63;
        int kc = r >> 5, j = r & 31;
        float bc = bias[c];
        float v0 = stage[c*132 + kc*64 + 2*j]     + bc;
        float v1 = stage[c*132 + kc*64 + 2*j + 1] + bc;
        if (rel) {
            v0 += rel[c*128 + kc*64 + 2*j];
            v1 += rel[c*128 + kc*64 + 2*j + 1];
        }
        unsigned hw = packh(v0, v1);
        size_t o = (size_t)((b*128 + c)*2 + kc)*TILE_W + q2*PW + j;
        dth[o] = hw;
        dtl[o] = packl(v0, v1, hw);
    }
}

// ----------------- bilinear gather -----------------
__global__ void __launch_bounds__(256) sample_kernel(const float* __restrict__ x) {
    int tid = threadIdx.x;
    int lane = tid & 31, wa = tid >> 5;
    int b = blockIdx.x >> 7, h = blockIdx.x & 127;
    const float* xb = x + (size_t)b*2097152;
    for (int w = wa; w < 128; w += 8) {
        size_t p = ((size_t)(b*128 + h))*128 + w;
        float xg = g_coords[2*p], yg = g_coords[2*p + 1];
        float x0 = floorf(xg), y0 = floorf(yg);
        float4 out = make_float4(0.f, 0.f, 0.f, 0.f);
#pragma unroll
        for (int dy = 0; dy < 2; dy++)
#pragma unroll
            for (int dx = 0; dx < 2; dx++) {
                float xi = x0 + (float)dx, yi = y0 + (float)dy;
                float wt = (1.f - fabsf(xg - xi))*(1.f - fabsf(yg - yi));
                bool valid = (xi >= 0.f) && (xi <= 127.f) && (yi >= 0.f) && (yi <= 127.f);
                float wv = valid ? wt : 0.f;
                int ix = min(max((int)xi, 0), 127);
                int iy = min(max((int)yi, 0), 127);
                float4 src = *(const float4*)(xb + ((size_t)(iy*128 + ix))*128 + lane*4);
                out.x += wv*src.x; out.y += wv*src.y; out.z += wv*src.z; out.w += wv*src.w;
            }
        *(float4*)(g_xs + p*128 + lane*4) = out;
    }
}

// ----------------- attention + fused output projection (R9 shapes, cached tiles) ----------
__global__ void __launch_bounds__(256) attn_kernel(const float* __restrict__ bo,
                                                   float* __restrict__ out) {
    extern __shared__ unsigned smw[];
    unsigned *Ah = smw, *Al = smw + TILE_W, *Bh = smw + 2*TILE_W, *Bl = smw + 3*TILE_W;
    unsigned sb = (unsigned)__cvta_generic_to_shared(smw);
    unsigned AhB = sb, AlB = sb + TILE_W*4, BhB = sb + 2*TILE_W*4, BlB = sb + 3*TILE_W*4;
    int tid = threadIdx.x, wid = tid >> 5, lane = tid & 31;
    int g = lane >> 2, tg = lane & 3;
    int s = blockIdx.x;
    int m0 = wid*16;

    // ---- S = qscaled @ k^T : tiles are pure copies ----
    float sacc[16][4] = {};
    for (int kc = 0; kc < 2; kc++) {
        size_t tb = (size_t)(s*2 + kc)*TILE_W;
        copy_tileN<TILE_W>(g_qth + tb, g_qtl + tb, Ah, Al, tid);
        copy_tileN<TILE_W>(g_kth + tb, g_ktl + tb, Bh, Bl, tid);
        __syncthreads();
        wgemm<1,16>(AhB, AlB, BhB, BlB, m0, 0, lane, sacc);
        __syncthreads();
    }

    // ---- softmax, rows m0+g and m0+g+8, reduce across quad (xor 1,2) ----
    float mx0 = -1e30f, mx1 = -1e30f;
#pragma unroll
    for (int nt = 0; nt < 16; nt++) {
        mx0 = fmaxf(mx0, fmaxf(sacc[nt][0], sacc[nt][1]));
        mx1 = fmaxf(mx1, fmaxf(sacc[nt][2], sacc[nt][3]));
    }
    mx0 = fmaxf(mx0, __shfl_xor_sync(~0u, mx0, 1)); mx0 = fmaxf(mx0, __shfl_xor_sync(~0u, mx0, 2));
    mx1 = fmaxf(mx1, __shfl_xor_sync(~0u, mx1, 1)); mx1 = fmaxf(mx1, __shfl_xor_sync(~0u, mx1, 2));
    float s0 = 0.f, s1 = 0.f;
#pragma unroll
    for (int nt = 0; nt < 16; nt++) {
        sacc[nt][0] = __expf(sacc[nt][0] - mx0); s0 += sacc[nt][0];
        sacc[nt][1] = __expf(sacc[nt][1] - mx0); s0 += sacc[nt][1];
        sacc[nt][2] = __expf(sacc[nt][2] - mx1); s1 += sacc[nt][2];
        sacc[nt][3] = __expf(sacc[nt][3] - mx1); s1 += sacc[nt][3];
    }
    s0 += __shfl_xor_sync(~0u, s0, 1); s0 += __shfl_xor_sync(~0u, s0, 2);
    s1 += __shfl_xor_sync(~0u, s1, 1); s1 += __shfl_xor_sync(~0u, s1, 2);
    float inv0 = 1.f/s0, inv1 = 1.f/s1;

    // ---- PV = P @ vT^T : P chunk -> A tiles, B = cached vT chunk ----
    float acc2[16][4] = {};
    for (int kc = 0; kc < 2; kc++) {
#pragma unroll
        for (int nt = 8*kc; nt < 8*kc + 8; nt++) {
            int wcol = (nt - 8*kc)*4 + tg;
            float p0 = sacc[nt][0]*inv0, p1 = sacc[nt][1]*inv0;
            float p2 = sacc[nt][2]*inv1, p3 = sacc[nt][3]*inv1;
            unsigned h0 = packh(p0, p1), h1 = packh(p2, p3);
            int o0 = (m0 + g)*PW + wcol, o1 = (m0 + g + 8)*PW + wcol;
            Ah[o0] = h0; Al[o0] = packl(p0, p1, h0);
            Ah[o1] = h1; Al[o1] = packl(p2, p3, h1);
        }
        size_t tb = (size_t)(s*2 + kc)*TILE_W;
        copy_tileN<TILE_W>(g_vth + tb, g_vtl + tb, Bh, Bl, tid);
        __syncthreads();
        wgemm<1,16>(AhB, AlB, BhB, BlB, m0, 0, lane, acc2);
        __syncthreads();
    }

    // ---- O = PV @ Wo^T : PV chunk -> A tiles, B = preconverted Wo chunk ----
    float acc3[16][4] = {};
    for (int kc = 0; kc < 2; kc++) {
#pragma unroll
        for (int nt = 8*kc; nt < 8*kc + 8; nt++) {
            int wcol = (nt - 8*kc)*4 + tg;
            float p0 = acc2[nt][0], p1 = acc2[nt][1];
            float p2 = acc2[nt][2], p3 = acc2[nt][3];
            unsigned h0 = packh(p0, p1), h1 = packh(p2, p3);
            int o0 = (m0 + g)*PW + wcol, o1 = (m0 + g + 8)*PW + wcol;
            Ah[o0] = h0; Al[o0] = packl(p0, p1, h0);
            Ah[o1] = h1; Al[o1] = packl(p2, p3, h1);
        }
        copy_tileN<TILE_W>(g_Wth[2][kc], g_Wtl[2][kc], Bh, Bl, tid);
        __syncthreads();
        wgemm<1,16>(AhB, AlB, BhB, BlB, m0, 0, lane, acc3);
        __syncthreads();
    }

    // ---- epilogue: out[s*128 + m][n] = O + bo ----
    float* ob = out + (size_t)s*16384;
#pragma unroll
    for (int nt = 0; nt < 16; nt++) {
        int n = nt*8 + 2*tg, m = m0 + g;
        float b0 = bo[n], b1 = bo[n+1];
        *(float2*)(ob + (size_t)m*128 + n)     = make_float2(acc3[nt][0] + b0, acc3[nt][1] + b1);
        *(float2*)(ob + (size_t)(m+8)*128 + n) = make_float2(acc3[nt][2] + b0, acc3[nt][3] + b1);
    }
}

// ----------------- launch -----------------
extern "C" void kernel_launch(void* const* d_in, const int* in_sizes, int n_in,
                              void* d_out, int out_size) {
    const float* x   = (const float*)d_in[0];
    const float* Wq  = (const float*)d_in[2];
    const float* bq  = (const float*)d_in[3];
    const float* Wk  = (const float*)d_in[4];
    const float* bk  = (const float*)d_in[5];
    const float* Wv  = (const float*)d_in[6];
    const float* bv  = (const float*)d_in[7];
    const float* Wo  = (const float*)d_in[8];
    const float* bo  = (const float*)d_in[9];
    const float* Wc1 = (const float*)d_in[10];
    const float* bc1 = (const float*)d_in[11];
    const float* Wc2 = (const float*)d_in[12];
    const float* rb  = (const float*)d_in[13];
    float* out = (float*)d_out;

    cudaFuncSetAttribute(qproj_kernel, cudaFuncAttributeMaxDynamicSharedMemorySize, SMEM_Q);
    cudaFuncSetAttribute(pk_kernel,    cudaFuncAttributeMaxDynamicSharedMemorySize, SMEM_SZ);
    cudaFuncSetAttribute(attn_kernel,  cudaFuncAttributeMaxDynamicSharedMemorySize, SMEM_SZ);

    prep_kernel   <<<51,  256>>>(Wq, Wc1, Wc2, bc1);
    prep2_kernel  <<<50,  128>>>(Wq, bq);
    prepW_kernel  <<<8,   256>>>(Wk, Wv, Wo);
    qproj_kernel  <<<512, 256, SMEM_Q>>>(x, bq);
    offset2_kernel<<<256, 256>>>();
    sample_kernel <<<512, 256>>>(x);
    pk_kernel     <<<512, 256, SMEM_SZ>>>(16384, 128,   0, 0, bk, nullptr);  // k per (b,h)
    pk_kernel     <<<512, 256, SMEM_SZ>>>(128,   16384, 1, 1, bv, rb);       // vT per (b,w)
    attn_kernel   <<<512, 256, SMEM_SZ>>>(bo, out);
}

// round 14
// speedup vs baseline: 1.2118x; 1.2118x over previous
#include <cuda_runtime.h>
#include <math.h>
#include <stdint.h>

#define ATT_SCALE 0.08838834764831845f   // 128^-0.5
#define PW 36                            // u32-word pitch of bf16 tiles (4 mod 32 -> conflict-free)

#define TILE_W  (128*PW)                 // 4608 words per 128-row tile
#define TILEQ_W (192*PW)                 // 6912 words per 192-row tile
#define SMEM_ATT 73728                   // attn: 4 x 128-row tiles
#define SMEM_PK  110592                  // pk: A pair + 2 chunk B pairs (6 tiles)
#define SMEM_Q   147456                  // qproj: A pair + 2 chunk 192-row B pairs

// ----------------- scratch (device globals; only referenced from device code) -----------------
__device__ __align__(128) float g_q  [4*128*16384];   // (B,C,H,W)
__device__ __align__(128) float g_k  [4*128*16384];   // (B,C,H,W)
__device__ __align__(128) float g_vT [4*128*16384];   // (B,C,W,H)
__device__ __align__(128) float g_xs [65536*128];     // (B,H,W,C)
__device__ __align__(128) float g_z  [4*64*16384];    // 50 offset-tap projections per batch
__device__ __align__(128) float g_coords[65536*2];
__device__ __align__(128) float g_Weff[50*128];
__device__ __align__(128) float g_zbias[50];
__device__ __align__(128) float g_beff[2];
__device__ __align__(128) float g_Wqz[192*128];
__device__ __align__(128) unsigned g_WthQ[2][TILEQ_W];
__device__ __align__(128) unsigned g_WtlQ[2][TILEQ_W];
__device__ __align__(128) unsigned g_Wth[3][2][TILE_W];   // 0=Wk, 1=Wv, 2=Wo
__device__ __align__(128) unsigned g_Wtl[3][2][TILE_W];

// ----------------- helpers -----------------
static __device__ __forceinline__ void mmabf(float c[4], const unsigned a[4],
                                             unsigned b0, unsigned b1) {
    asm volatile("mma.sync.aligned.m16n8k16.row.col.f32.bf16.bf16.f32 "
        "{%0,%1,%2,%3},{%4,%5,%6,%7},{%8,%9},{%0,%1,%2,%3};"
        : "+f"(c[0]), "+f"(c[1]), "+f"(c[2]), "+f"(c[3])
        : "r"(a[0]), "r"(a[1]), "r"(a[2]), "r"(a[3]), "r"(b0), "r"(b1));
}
static __device__ __forceinline__ void ldsm4(unsigned r[4], unsigned addr) {
    asm volatile("ldmatrix.sync.aligned.m8n8.x4.shared.b16 {%0,%1,%2,%3},[%4];"
        : "=r"(r[0]), "=r"(r[1]), "=r"(r[2]), "=r"(r[3]) : "r"(addr));
}
static __device__ __forceinline__ unsigned packh(float x0, float x1) {
    unsigned h; asm("cvt.rn.bf16x2.f32 %0,%1,%2;" : "=r"(h) : "f"(x1), "f"(x0)); return h;
}
static __device__ __forceinline__ unsigned packl(float x0, float x1, unsigned h) {
    float h0 = __uint_as_float(h << 16), h1 = __uint_as_float(h & 0xffff0000u);
    return packh(x0 - h0, x1 - h1);
}
static __device__ __forceinline__ void cpa16(unsigned dst, const void* src) {
    asm volatile("cp.async.cg.shared.global [%0], [%1], 16;" :: "r"(dst), "l"(src));
}
static __device__ __forceinline__ void cpa_commit() {
    asm volatile("cp.async.commit_group;" ::: "memory");
}
static __device__ __forceinline__ void cpa_wait0() {
    asm volatile("cp.async.wait_group 0;" ::: "memory");
}

// load a ROWSx64 fp32 chunk (cols kc*64..) into hi/lo bf16-pair word tiles; 256 threads
template<int ROWS>
static __device__ __forceinline__ void fill_chunkR(const float* __restrict__ src, int ld, int kc,
                                                   float scale, unsigned* th, unsigned* tl, int tid) {
#pragma unroll
    for (int it = 0; it < ROWS/16; it++) {
        int idx = it*256 + tid;
        int r = idx >> 4, c4 = (idx & 15)*4;
        float4 v = *(const float4*)(src + (size_t)r*ld + kc*64 + c4);
        float x0 = v.x*scale, x1 = v.y*scale, x2 = v.z*scale, x3 = v.w*scale;
        unsigned h0 = packh(x0, x1), h1 = packh(x2, x3);
        unsigned l0 = packl(x0, x1, h0), l1 = packl(x2, x3, h1);
        int o = r*PW + (c4 >> 1);
        th[o] = h0; th[o+1] = h1;
        tl[o] = l0; tl[o+1] = l1;
    }
}

// copy a preconverted NW-word tile pair (global -> smem); 256 threads (synchronous path, attn)
template<int NW>
static __device__ __forceinline__ void copy_tileN(const unsigned* __restrict__ gh,
                                                  const unsigned* __restrict__ gl,
                                                  unsigned* th, unsigned* tl, int tid) {
#pragma unroll
    for (int it = 0; it < (NW/4 + 255)/256; it++) {
        int idx = it*256 + tid;
        if (idx < NW/4) {
            ((uint4*)th)[idx] = ((const uint4*)gh)[idx];
            ((uint4*)tl)[idx] = ((const uint4*)gl)[idx];
        }
    }
}

// async prefetch of BOTH chunks of a weight tile pair set (4 tiles of NW words); 256 threads
template<int NW>
static __device__ __forceinline__ void prefetch_B2(const unsigned* __restrict__ h0,
                                                   const unsigned* __restrict__ l0,
                                                   const unsigned* __restrict__ h1,
                                                   const unsigned* __restrict__ l1,
                                                   unsigned dstb,   // smem byte addr of first tile
                                                   int tid) {
    const unsigned* srcs[4] = {h0, l0, h1, l1};
    const int NV = NW/4;                    // uint4 per tile
#pragma unroll
    for (int it = 0; it < 4*NV/256; it++) {
        int idx = it*256 + tid;
        int t = idx / NV, off = idx - t*NV;
        cpa16(dstb + (unsigned)(t*NW + off*4)*4u, srcs[t] + (size_t)off*4);
    }
    cpa_commit();
}

// warp GEMM over one K=64 chunk via ldmatrix: C[m0..+MT*16][n0..+NT*8] += A @ B^T (bf16x3)
template<int MT, int NT>
static __device__ __forceinline__ void wgemm(unsigned AhB, unsigned AlB,
                                             unsigned BhB, unsigned BlB,
                                             int m0, int n0, int lane, float (*acc)[4]) {
    unsigned aoff = ((m0 + ((lane>>3)&1)*8 + (lane&7))*PW + ((lane>>4)<<2))*4;
    unsigned boff = ((n0 + (lane>>4)*8 + (lane&7))*PW + (((lane>>3)&1)<<2))*4;
#pragma unroll
    for (int ks = 0; ks < 4; ks++) {
        unsigned ka = ks*32;
        unsigned ah[MT][4], al[MT][4];
#pragma unroll
        for (int mt = 0; mt < MT; mt++) {
            ldsm4(ah[mt], AhB + aoff + mt*(16*PW*4) + ka);
            ldsm4(al[mt], AlB + aoff + mt*(16*PW*4) + ka);
        }
#pragma unroll
        for (int ntp = 0; ntp < NT/2; ntp++) {
            unsigned bh[4], bl[4];
            unsigned bo = boff + ntp*(16*PW*4) + ka;
            ldsm4(bh, BhB + bo);
            ldsm4(bl, BlB + bo);
#pragma unroll
            for (int mt = 0; mt < MT; mt++) {
                float* c0 = acc[mt*NT + 2*ntp];
                float* c1 = acc[mt*NT + 2*ntp + 1];
                mmabf(c0, ah[mt], bh[0], bh[1]);
                mmabf(c0, ah[mt], bl[0], bl[1]);
                mmabf(c0, al[mt], bh[0], bh[1]);
                mmabf(c1, ah[mt], bh[2], bh[3]);
                mmabf(c1, ah[mt], bl[2], bl[3]);
                mmabf(c1, al[mt], bh[2], bh[3]);
            }
        }
    }
}

// ----------------- prep: Weff fold, Wq copy, zero pad, beff -----------------
__global__ void prep_kernel(const float* __restrict__ Wq, const float* __restrict__ Wc1,
                            const float* __restrict__ Wc2, const float* __restrict__ bc1) {
    int blk = blockIdx.x, tid = threadIdx.x;
    if (blk < 50) {
        int j = blk / 25, t = blk % 25;
        if (tid < 128) {
            float s = 0.f;
            for (int o = 0; o < 128; o++)
                s += Wc2[j*128 + o] * Wc1[((size_t)(o*128 + tid))*25 + t];
            g_Weff[blk*128 + tid] = s;
        }
    } else {
        for (int i = tid; i < 16384; i += 256) g_Wqz[i] = Wq[i];
        for (int i = tid; i < 14*128; i += 256) g_Wqz[178*128 + i] = 0.f;
        if (tid < 2) {
            float s = 0.f;
            for (int o = 0; o < 128; o++) s += Wc2[tid*128 + o] * bc1[o];
            g_beff[tid] = s;
        }
    }
}

// ----------------- prep2: Wz = Weff @ Wq ; zbias = Weff @ bq -----------------
__global__ void prep2_kernel(const float* __restrict__ Wq, const float* __restrict__ bq) {
    int jt = blockIdx.x, tid = threadIdx.x;
    float s = 0.f;
    for (int c = 0; c < 128; c++) s += g_Weff[jt*128 + c] * Wq[c*128 + tid];
    g_Wqz[(128 + jt)*128 + tid] = s;
    if (tid == 0) {
        float z = 0.f;
        for (int c = 0; c < 128; c++) z += g_Weff[jt*128 + c] * bq[c];
        g_zbias[jt] = z;
    }
}

// ----------------- prepW: convert weights to hi/lo word tiles -----------------
__global__ void prepW_kernel(const float* __restrict__ Wk, const float* __restrict__ Wv,
                             const float* __restrict__ Wo) {
    int blk = blockIdx.x, tid = threadIdx.x;    // 8 blocks
    if (blk < 2) {
        fill_chunkR<192>(g_Wqz, 128, blk, 1.f, g_WthQ[blk], g_WtlQ[blk], tid);
    } else {
        int w = (blk - 2) >> 1, kc = (blk - 2) & 1;
        const float* W = (w == 0) ? Wk : (w == 1) ? Wv : Wo;
        fill_chunkR<128>(W, 128, kc, 1.f, g_Wth[w][kc], g_Wtl[w][kc], tid);
    }
}

// ----------------- qproj: [q | z] = x_slice @ [Wq;Wz]^T, N=192, B prefetched async ----------
__global__ void __launch_bounds__(256) qproj_kernel(const float* __restrict__ x,
                                                    const float* __restrict__ bq) {
    extern __shared__ unsigned smw[];
    unsigned *Ah = smw, *Al = smw + TILE_W;
    unsigned sb = (unsigned)__cvta_generic_to_shared(smw);
    unsigned AhB = sb, AlB = sb + TILE_W*4;
    unsigned Bbase = sb + 2*TILE_W*4;
    int tid = threadIdx.x, wid = tid >> 5, lane = tid & 31;
    int g = lane >> 2, tg = lane & 3;
    int b = blockIdx.x >> 7, h = blockIdx.x & 127;
    const float* src = x + (size_t)b*2097152 + (size_t)h*16384;

    // async prefetch both 192-row B chunk tile pairs
    prefetch_B2<TILEQ_W>(g_WthQ[0], g_WtlQ[0], g_WthQ[1], g_WtlQ[1], Bbase, tid);

    float acc[24][4] = {};
    int m0 = (wid >> 1)*32, n0 = (wid & 1)*96;

    fill_chunkR<128>(src, 128, 0, 1.f, Ah, Al, tid);
    cpa_wait0();
    __syncthreads();
    wgemm<2,12>(AhB, AlB, Bbase, Bbase + TILEQ_W*4, m0, n0, lane, acc);
    __syncthreads();
    fill_chunkR<128>(src, 128, 1, 1.f, Ah, Al, tid);
    __syncthreads();
    wgemm<2,12>(AhB, AlB, Bbase + 2*TILEQ_W*4, Bbase + 3*TILEQ_W*4, m0, n0, lane, acc);
    __syncthreads();

    // stage transposed [n][m], pitch 132, 192 rows
    float* stage = (float*)smw;
#pragma unroll
    for (int mt = 0; mt < 2; mt++)
#pragma unroll
        for (int nt = 0; nt < 12; nt++) {
            int m = m0 + mt*16 + g, n = n0 + nt*8 + 2*tg;
            stage[n*132 + m]         = acc[mt*12+nt][0];
            stage[(n+1)*132 + m]     = acc[mt*12+nt][1];
            stage[n*132 + m + 8]     = acc[mt*12+nt][2];
            stage[(n+1)*132 + m + 8] = acc[mt*12+nt][3];
        }
    __syncthreads();

    float* qd = g_q + (size_t)b*2097152 + (size_t)h*128;
#pragma unroll
    for (int it = 0; it < 16; it++) {
        int idx = it*256 + tid;
        int c = idx >> 5, m4 = (idx & 31)*4;
        float bias = bq[c];
        float4 v = *(float4*)(stage + c*132 + m4);
        v.x += bias; v.y += bias; v.z += bias; v.w += bias;
        *(float4*)(qd + (size_t)c*16384 + m4) = v;
    }
    float* zd = g_z + (size_t)b*1048576 + (size_t)h*128;
#pragma unroll
    for (int it = 0; it < 7; it++) {
        int idx = it*256 + tid;
        if (idx < 1600) {
            int zr = idx >> 5, m4 = (idx & 31)*4;
            float4 v = *(float4*)(stage + (128 + zr)*132 + m4);
            *(float4*)(zd + (size_t)zr*16384 + m4) = v;
        }
    }
}

// ----------------- offset2: 25-tap shifted sum over z + coords -----------------
__global__ void __launch_bounds__(256) offset2_kernel() {
    int p = blockIdx.x*256 + threadIdx.x;
    int b = p >> 14, rem = p & 16383;
    int h = rem >> 7, w = rem & 127;
    const float* zb = g_z + (size_t)b*1048576;
    float a0 = g_beff[0], a1 = g_beff[1];
#pragma unroll
    for (int kh = 0; kh < 5; kh++) {
        int hh = h + kh - 2;
        if ((unsigned)hh > 127u) continue;
#pragma unroll
        for (int kw = 0; kw < 5; kw++) {
            int ww = w + kw - 2;
            if ((unsigned)ww > 127u) continue;
            int t = kh*5 + kw, sp = hh*128 + ww;
            a0 += zb[(size_t)t*16384 + sp]        + g_zbias[t];
            a1 += zb[(size_t)(25 + t)*16384 + sp] + g_zbias[25 + t];
        }
    }
    float off0 = tanhf(a0)*5.f, off1 = tanhf(a1)*5.f;
    g_coords[2*p]     = ((float)w + off0)*(128.f/127.f) - 0.5f;
    g_coords[2*p + 1] = ((float)h + off1)*(128.f/127.f) - 0.5f;
}

// ----------------- merged k + vT projection, 1024 blocks, 2 CTAs/SM -----------------
__global__ void __launch_bounds__(256,2) pk_kernel(const float* __restrict__ bk,
                                                   const float* __restrict__ bv,
                                                   const float* __restrict__ rel) {
    extern __shared__ unsigned smw[];
    unsigned *Ah = smw, *Al = smw + TILE_W;
    unsigned sb = (unsigned)__cvta_generic_to_shared(smw);
    unsigned AhB = sb, AlB = sb + TILE_W*4;
    unsigned Bbase = sb + 2*TILE_W*4;
    int tid = threadIdx.x, wid = tid >> 5, lane = tid & 31;
    int g = lane >> 2, tg = lane & 3;
    int gb = blockIdx.x;
    int wsel = gb >> 9;                  // 0 = k, 1 = vT
    int q = gb & 511;
    int b = q >> 7, q2 = q & 127;
    int blk_mul = wsel ? 128 : 16384;
    int row_mul = wsel ? 16384 : 128;
    const float* bias = wsel ? bv : bk;
    const float* src = g_xs + (size_t)b*2097152 + (size_t)q2*blk_mul;
    float* dst = wsel ? g_vT : g_k;

    prefetch_B2<TILE_W>(g_Wth[wsel][0], g_Wtl[wsel][0], g_Wth[wsel][1], g_Wtl[wsel][1],
                        Bbase, tid);

    float acc[16][4] = {};
    int m0 = (wid >> 1)*32, n0 = (wid & 1)*64;

    fill_chunkR<128>(src, row_mul, 0, 1.f, Ah, Al, tid);
    cpa_wait0();
    __syncthreads();
    wgemm<2,8>(AhB, AlB, Bbase, Bbase + TILE_W*4, m0, n0, lane, acc);
    __syncthreads();
    fill_chunkR<128>(src, row_mul, 1, 1.f, Ah, Al, tid);
    __syncthreads();
    wgemm<2,8>(AhB, AlB, Bbase + 2*TILE_W*4, Bbase + 3*TILE_W*4, m0, n0, lane, acc);
    __syncthreads();

    float* stage = (float*)smw;
#pragma unroll
    for (int mt = 0; mt < 2; mt++)
#pragma unroll
        for (int nt = 0; nt < 8; nt++) {
            int m = m0 + mt*16 + g, n = n0 + nt*8 + 2*tg;
            stage[n*132 + m]         = acc[mt*8+nt][0];
            stage[(n+1)*132 + m]     = acc[mt*8+nt][1];
            stage[n*132 + m + 8]     = acc[mt*8+nt][2];
            stage[(n+1)*132 + m + 8] = acc[mt*8+nt][3];
        }
    __syncthreads();

    float* db = dst + (size_t)b*2097152 + (size_t)q2*128;
#pragma unroll
    for (int it = 0; it < 16; it++) {
        int idx = it*256 + tid;
        int c = idx >> 5, m4 = (idx & 31)*4;
        float bc = bias[c];
        float4 v = *(float4*)(stage + c*132 + m4);
        if (wsel) {
            float4 rv = *(const float4*)(rel + c*128 + m4);
            v.x += bc + rv.x; v.y += bc + rv.y; v.z += bc + rv.z; v.w += bc + rv.w;
        } else {
            v.x += bc; v.y += bc; v.z += bc; v.w += bc;
        }
        *(float4*)(db + (size_t)c*16384 + m4) = v;
    }
}

// ----------------- bilinear gather -----------------
__global__ void __launch_bounds__(256) sample_kernel(const float* __restrict__ x) {
    int tid = threadIdx.x;
    int lane = tid & 31, wa = tid >> 5;
    int b = blockIdx.x >> 7, h = blockIdx.x & 127;
    const float* xb = x + (size_t)b*2097152;
    for (int w = wa; w < 128; w += 8) {
        size_t p = ((size_t)(b*128 + h))*128 + w;
        float xg = g_coords[2*p], yg = g_coords[2*p + 1];
        float x0 = floorf(xg), y0 = floorf(yg);
        float4 out = make_float4(0.f, 0.f, 0.f, 0.f);
#pragma unroll
        for (int dy = 0; dy < 2; dy++)
#pragma unroll
            for (int dx = 0; dx < 2; dx++) {
                float xi = x0 + (float)dx, yi = y0 + (float)dy;
                float wt = (1.f - fabsf(xg - xi))*(1.f - fabsf(yg - yi));
                bool valid = (xi >= 0.f) && (xi <= 127.f) && (yi >= 0.f) && (yi <= 127.f);
                float wv = valid ? wt : 0.f;
                int ix = min(max((int)xi, 0), 127);
                int iy = min(max((int)yi, 0), 127);
                float4 src = *(const float4*)(xb + ((size_t)(iy*128 + ix))*128 + lane*4);
                out.x += wv*src.x; out.y += wv*src.y; out.z += wv*src.z; out.w += wv*src.w;
            }
        *(float4*)(g_xs + p*128 + lane*4) = out;
    }
}

// ----------------- attention + fused output projection (R9-exact) -----------------
__global__ void __launch_bounds__(256) attn_kernel(const float* __restrict__ bo,
                                                   float* __restrict__ out) {
    extern __shared__ unsigned smw[];
    unsigned *Ah = smw, *Al = smw + TILE_W, *Bh = smw + 2*TILE_W, *Bl = smw + 3*TILE_W;
    unsigned sb = (unsigned)__cvta_generic_to_shared(smw);
    unsigned AhB = sb, AlB = sb + TILE_W*4, BhB = sb + 2*TILE_W*4, BlB = sb + 3*TILE_W*4;
    int tid = threadIdx.x, wid = tid >> 5, lane = tid & 31;
    int g = lane >> 2, tg = lane & 3;
    int s = blockIdx.x;
    const float* qs = g_q  + (size_t)s*16384;
    const float* ks = g_k  + (size_t)s*16384;
    const float* vs = g_vT + (size_t)s*16384;
    int m0 = wid*16;

    // ---- S = (q*scale) @ k^T ----
    float sacc[16][4] = {};
    for (int kc = 0; kc < 2; kc++) {
        fill_chunkR<128>(qs, 128, kc, ATT_SCALE, Ah, Al, tid);
        fill_chunkR<128>(ks, 128, kc, 1.f,       Bh, Bl, tid);
        __syncthreads();
        wgemm<1,16>(AhB, AlB, BhB, BlB, m0, 0, lane, sacc);
        __syncthreads();
    }

    // ---- softmax ----
    float mx0 = -1e30f, mx1 = -1e30f;
#pragma unroll
    for (int nt = 0; nt < 16; nt++) {
        mx0 = fmaxf(mx0, fmaxf(sacc[nt][0], sacc[nt][1]));
        mx1 = fmaxf(mx1, fmaxf(sacc[nt][2], sacc[nt][3]));
    }
    mx0 = fmaxf(mx0, __shfl_xor_sync(~0u, mx0, 1)); mx0 = fmaxf(mx0, __shfl_xor_sync(~0u, mx0, 2));
    mx1 = fmaxf(mx1, __shfl_xor_sync(~0u, mx1, 1)); mx1 = fmaxf(mx1, __shfl_xor_sync(~0u, mx1, 2));
    float s0 = 0.f, s1 = 0.f;
#pragma unroll
    for (int nt = 0; nt < 16; nt++) {
        sacc[nt][0] = __expf(sacc[nt][0] - mx0); s0 += sacc[nt][0];
        sacc[nt][1] = __expf(sacc[nt][1] - mx0); s0 += sacc[nt][1];
        sacc[nt][2] = __expf(sacc[nt][2] - mx1); s1 += sacc[nt][2];
        sacc[nt][3] = __expf(sacc[nt][3] - mx1); s1 += sacc[nt][3];
    }
    s0 += __shfl_xor_sync(~0u, s0, 1); s0 += __shfl_xor_sync(~0u, s0, 2);
    s1 += __shfl_xor_sync(~0u, s1, 1); s1 += __shfl_xor_sync(~0u, s1, 2);
    float inv0 = 1.f/s0, inv1 = 1.f/s1;

    // ---- PV = P @ vT^T ----
    float acc2[16][4] = {};
    for (int kc = 0; kc < 2; kc++) {
#pragma unroll
        for (int nt = 8*kc; nt < 8*kc + 8; nt++) {
            int wcol = (nt - 8*kc)*4 + tg;
            float p0 = sacc[nt][0]*inv0, p1 = sacc[nt][1]*inv0;
            float p2 = sacc[nt][2]*inv1, p3 = sacc[nt][3]*inv1;
            unsigned h0 = packh(p0, p1), h1 = packh(p2, p3);
            int o0 = (m0 + g)*PW + wcol, o1 = (m0 + g + 8)*PW + wcol;
            Ah[o0] = h0; Al[o0] = packl(p0, p1, h0);
            Ah[o1] = h1; Al[o1] = packl(p2, p3, h1);
        }
        fill_chunkR<128>(vs, 128, kc, 1.f, Bh, Bl, tid);
        __syncthreads();
        wgemm<1,16>(AhB, AlB, BhB, BlB, m0, 0, lane, acc2);
        __syncthreads();
    }

    // ---- O = PV @ Wo^T ----
    float acc3[16][4] = {};
    for (int kc = 0; kc < 2; kc++) {
#pragma unroll
        for (int nt = 8*kc; nt < 8*kc + 8; nt++) {
            int wcol = (nt - 8*kc)*4 + tg;
            float p0 = acc2[nt][0], p1 = acc2[nt][1];
            float p2 = acc2[nt][2], p3 = acc2[nt][3];
            unsigned h0 = packh(p0, p1), h1 = packh(p2, p3);
            int o0 = (m0 + g)*PW + wcol, o1 = (m0 + g + 8)*PW + wcol;
            Ah[o0] = h0; Al[o0] = packl(p0, p1, h0);
            Ah[o1] = h1; Al[o1] = packl(p2, p3, h1);
        }
        copy_tileN<TILE_W>(g_Wth[2][kc], g_Wtl[2][kc], Bh, Bl, tid);
        __syncthreads();
        wgemm<1,16>(AhB, AlB, BhB, BlB, m0, 0, lane, acc3);
        __syncthreads();
    }

    // ---- epilogue ----
    float* ob = out + (size_t)s*16384;
#pragma unroll
    for (int nt = 0; nt < 16; nt++) {
        int n = nt*8 + 2*tg, m = m0 + g;
        float b0 = bo[n], b1 = bo[n+1];
        *(float2*)(ob + (size_t)m*128 + n)     = make_float2(acc3[nt][0] + b0, acc3[nt][1] + b1);
        *(float2*)(ob + (size_t)(m+8)*128 + n) = make_float2(acc3[nt][2] + b0, acc3[nt][3] + b1);
    }
}

// ----------------- launch -----------------
extern "C" void kernel_launch(void* const* d_in, const int* in_sizes, int n_in,
                              void* d_out, int out_size) {
    const float* x   = (const float*)d_in[0];
    const float* Wq  = (const float*)d_in[2];
    const float* bq  = (const float*)d_in[3];
    const float* Wk  = (const float*)d_in[4];
    const float* bk  = (const float*)d_in[5];
    const float* Wv  = (const float*)d_in[6];
    const float* bv  = (const float*)d_in[7];
    const float* Wo  = (const float*)d_in[8];
    const float* bo  = (const float*)d_in[9];
    const float* Wc1 = (const float*)d_in[10];
    const float* bc1 = (const float*)d_in[11];
    const float* Wc2 = (const float*)d_in[12];
    const float* rb  = (const float*)d_in[13];
    float* out = (float*)d_out;

    cudaFuncSetAttribute(qproj_kernel, cudaFuncAttributeMaxDynamicSharedMemorySize, SMEM_Q);
    cudaFuncSetAttribute(pk_kernel,    cudaFuncAttributeMaxDynamicSharedMemorySize, SMEM_PK);
    cudaFuncSetAttribute(attn_kernel,  cudaFuncAttributeMaxDynamicSharedMemorySize, SMEM_ATT);

    prep_kernel   <<<51,   256>>>(Wq, Wc1, Wc2, bc1);
    prep2_kernel  <<<50,   128>>>(Wq, bq);
    prepW_kernel  <<<8,    256>>>(Wk, Wv, Wo);
    qproj_kernel  <<<512,  256, SMEM_Q>>>(x, bq);
    offset2_kernel<<<256,  256>>>();
    sample_kernel <<<512,  256>>>(x);
    pk_kernel     <<<1024, 256, SMEM_PK>>>(bk, bv, rb);
    attn_kernel   <<<512,  256, SMEM_ATT>>>(bo, out);
}

// round 15
// speedup vs baseline: 1.2637x; 1.0428x over previous
#include <cuda_runtime.h>
#include <math.h>
#include <stdint.h>

#define ATT_SCALE 0.08838834764831845f   // 128^-0.5
#define PW 36                            // u32-word pitch of bf16 tiles (4 mod 32 -> conflict-free)

#define TILE_W  (128*PW)                 // 4608 words per 128-row tile
#define TILEQ_W (192*PW)                 // 6912 words per 192-row tile
#define SMEM_ATT 221184                  // attn: 12 x 128-row tiles (A0,A1,Bk0,Bk1,Bv0,Bv1 pairs)
#define SMEM_PK  110592                  // pk: A pair + 2 chunk B pairs
#define SMEM_Q   184320                  // qproj: 2 A pairs + 2 chunk 192-row B pairs

// ----------------- scratch (device globals; only referenced from device code) -----------------
__device__ __align__(128) float g_q  [4*128*16384];   // (B,C,H,W)
__device__ __align__(128) float g_k  [4*128*16384];   // (B,C,H,W)
__device__ __align__(128) float g_vT [4*128*16384];   // (B,C,W,H)
__device__ __align__(128) float g_xs [65536*128];     // (B,H,W,C)
__device__ __align__(128) float g_z  [4*64*16384];    // 50 offset-tap projections per batch
__device__ __align__(128) float g_coords[65536*2];
__device__ __align__(128) float g_Weff[50*128];
__device__ __align__(128) float g_zbias[50];
__device__ __align__(128) float g_beff[2];
__device__ __align__(128) float g_Wqz[192*128];
__device__ __align__(128) unsigned g_WthQ[2][TILEQ_W];
__device__ __align__(128) unsigned g_WtlQ[2][TILEQ_W];
__device__ __align__(128) unsigned g_Wth[3][2][TILE_W];   // 0=Wk, 1=Wv, 2=Wo
__device__ __align__(128) unsigned g_Wtl[3][2][TILE_W];

// ----------------- helpers -----------------
static __device__ __forceinline__ void mmabf(float c[4], const unsigned a[4],
                                             unsigned b0, unsigned b1) {
    asm volatile("mma.sync.aligned.m16n8k16.row.col.f32.bf16.bf16.f32 "
        "{%0,%1,%2,%3},{%4,%5,%6,%7},{%8,%9},{%0,%1,%2,%3};"
        : "+f"(c[0]), "+f"(c[1]), "+f"(c[2]), "+f"(c[3])
        : "r"(a[0]), "r"(a[1]), "r"(a[2]), "r"(a[3]), "r"(b0), "r"(b1));
}
static __device__ __forceinline__ void ldsm4(unsigned r[4], unsigned addr) {
    asm volatile("ldmatrix.sync.aligned.m8n8.x4.shared.b16 {%0,%1,%2,%3},[%4];"
        : "=r"(r[0]), "=r"(r[1]), "=r"(r[2]), "=r"(r[3]) : "r"(addr));
}
static __device__ __forceinline__ unsigned packh(float x0, float x1) {
    unsigned h; asm("cvt.rn.bf16x2.f32 %0,%1,%2;" : "=r"(h) : "f"(x1), "f"(x0)); return h;
}
static __device__ __forceinline__ unsigned packl(float x0, float x1, unsigned h) {
    float h0 = __uint_as_float(h << 16), h1 = __uint_as_float(h & 0xffff0000u);
    return packh(x0 - h0, x1 - h1);
}
static __device__ __forceinline__ void cpa16(unsigned dst, const void* src) {
    asm volatile("cp.async.cg.shared.global [%0], [%1], 16;" :: "r"(dst), "l"(src));
}
static __device__ __forceinline__ void cpa_commit() {
    asm volatile("cp.async.commit_group;" ::: "memory");
}
static __device__ __forceinline__ void cpa_wait0() {
    asm volatile("cp.async.wait_group 0;" ::: "memory");
}

// load a ROWSx64 fp32 chunk (cols kc*64..) into hi/lo bf16-pair word tiles; 256 threads
template<int ROWS>
static __device__ __forceinline__ void fill_chunkR(const float* __restrict__ src, int ld, int kc,
                                                   float scale, unsigned* th, unsigned* tl, int tid) {
#pragma unroll
    for (int it = 0; it < ROWS/16; it++) {
        int idx = it*256 + tid;
        int r = idx >> 4, c4 = (idx & 15)*4;
        float4 v = *(const float4*)(src + (size_t)r*ld + kc*64 + c4);
        float x0 = v.x*scale, x1 = v.y*scale, x2 = v.z*scale, x3 = v.w*scale;
        unsigned h0 = packh(x0, x1), h1 = packh(x2, x3);
        unsigned l0 = packl(x0, x1, h0), l1 = packl(x2, x3, h1);
        int o = r*PW + (c4 >> 1);
        th[o] = h0; th[o+1] = h1;
        tl[o] = l0; tl[o+1] = l1;
    }
}

// async prefetch of BOTH chunks of a weight tile pair set (4 tiles of NW words); 256 threads
template<int NW>
static __device__ __forceinline__ void prefetch_B2(const unsigned* __restrict__ h0,
                                                   const unsigned* __restrict__ l0,
                                                   const unsigned* __restrict__ h1,
                                                   const unsigned* __restrict__ l1,
                                                   unsigned dstb, int tid) {
    const unsigned* srcs[4] = {h0, l0, h1, l1};
    const int NV = NW/4;
#pragma unroll
    for (int it = 0; it < 4*NV/256; it++) {
        int idx = it*256 + tid;
        int t = idx / NV, off = idx - t*NV;
        cpa16(dstb + (unsigned)(t*NW + off*4)*4u, srcs[t] + (size_t)off*4);
    }
    cpa_commit();
}

// warp GEMM over one K=64 chunk via ldmatrix: C[m0..+MT*16][n0..+NT*8] += A @ B^T (bf16x3)
template<int MT, int NT>
static __device__ __forceinline__ void wgemm(unsigned AhB, unsigned AlB,
                                             unsigned BhB, unsigned BlB,
                                             int m0, int n0, int lane, float (*acc)[4]) {
    unsigned aoff = ((m0 + ((lane>>3)&1)*8 + (lane&7))*PW + ((lane>>4)<<2))*4;
    unsigned boff = ((n0 + (lane>>4)*8 + (lane&7))*PW + (((lane>>3)&1)<<2))*4;
#pragma unroll
    for (int ks = 0; ks < 4; ks++) {
        unsigned ka = ks*32;
        unsigned ah[MT][4], al[MT][4];
#pragma unroll
        for (int mt = 0; mt < MT; mt++) {
            ldsm4(ah[mt], AhB + aoff + mt*(16*PW*4) + ka);
            ldsm4(al[mt], AlB + aoff + mt*(16*PW*4) + ka);
        }
#pragma unroll
        for (int ntp = 0; ntp < NT/2; ntp++) {
            unsigned bh[4], bl[4];
            unsigned bo = boff + ntp*(16*PW*4) + ka;
            ldsm4(bh, BhB + bo);
            ldsm4(bl, BlB + bo);
#pragma unroll
            for (int mt = 0; mt < MT; mt++) {
                float* c0 = acc[mt*NT + 2*ntp];
                float* c1 = acc[mt*NT + 2*ntp + 1];
                mmabf(c0, ah[mt], bh[0], bh[1]);
                mmabf(c0, ah[mt], bl[0], bl[1]);
                mmabf(c0, al[mt], bh[0], bh[1]);
                mmabf(c1, ah[mt], bh[2], bh[3]);
                mmabf(c1, ah[mt], bl[2], bl[3]);
                mmabf(c1, al[mt], bh[2], bh[3]);
            }
        }
    }
}

// ----------------- prep kernels (unchanged) -----------------
__global__ void prep_kernel(const float* __restrict__ Wq, const float* __restrict__ Wc1,
                            const float* __restrict__ Wc2, const float* __restrict__ bc1) {
    int blk = blockIdx.x, tid = threadIdx.x;
    if (blk < 50) {
        int j = blk / 25, t = blk % 25;
        if (tid < 128) {
            float s = 0.f;
            for (int o = 0; o < 128; o++)
                s += Wc2[j*128 + o] * Wc1[((size_t)(o*128 + tid))*25 + t];
            g_Weff[blk*128 + tid] = s;
        }
    } else {
        for (int i = tid; i < 16384; i += 256) g_Wqz[i] = Wq[i];
        for (int i = tid; i < 14*128; i += 256) g_Wqz[178*128 + i] = 0.f;
        if (tid < 2) {
            float s = 0.f;
            for (int o = 0; o < 128; o++) s += Wc2[tid*128 + o] * bc1[o];
            g_beff[tid] = s;
        }
    }
}
__global__ void prep2_kernel(const float* __restrict__ Wq, const float* __restrict__ bq) {
    int jt = blockIdx.x, tid = threadIdx.x;
    float s = 0.f;
    for (int c = 0; c < 128; c++) s += g_Weff[jt*128 + c] * Wq[c*128 + tid];
    g_Wqz[(128 + jt)*128 + tid] = s;
    if (tid == 0) {
        float z = 0.f;
        for (int c = 0; c < 128; c++) z += g_Weff[jt*128 + c] * bq[c];
        g_zbias[jt] = z;
    }
}
__global__ void prepW_kernel(const float* __restrict__ Wk, const float* __restrict__ Wv,
                             const float* __restrict__ Wo) {
    int blk = blockIdx.x, tid = threadIdx.x;
    if (blk < 2) {
        fill_chunkR<192>(g_Wqz, 128, blk, 1.f, g_WthQ[blk], g_WtlQ[blk], tid);
    } else {
        int w = (blk - 2) >> 1, kc = (blk - 2) & 1;
        const float* W = (w == 0) ? Wk : (w == 1) ? Wv : Wo;
        fill_chunkR<128>(W, 128, kc, 1.f, g_Wth[w][kc], g_Wtl[w][kc], tid);
    }
}

// ----------------- qproj: both A chunks upfront, B prefetched async -----------------
__global__ void __launch_bounds__(256) qproj_kernel(const float* __restrict__ x,
                                                    const float* __restrict__ bq) {
    extern __shared__ unsigned smw[];
    unsigned *A0h = smw,            *A0l = smw + TILE_W;
    unsigned *A1h = smw + 2*TILE_W, *A1l = smw + 3*TILE_W;
    unsigned sb = (unsigned)__cvta_generic_to_shared(smw);
    unsigned Bbase = sb + 4*TILE_W*4;
    int tid = threadIdx.x, wid = tid >> 5, lane = tid & 31;
    int g = lane >> 2, tg = lane & 3;
    int b = blockIdx.x >> 7, h = blockIdx.x & 127;
    const float* src = x + (size_t)b*2097152 + (size_t)h*16384;

    prefetch_B2<TILEQ_W>(g_WthQ[0], g_WtlQ[0], g_WthQ[1], g_WtlQ[1], Bbase, tid);

    fill_chunkR<128>(src, 128, 0, 1.f, A0h, A0l, tid);
    fill_chunkR<128>(src, 128, 1, 1.f, A1h, A1l, tid);
    cpa_wait0();
    __syncthreads();

    float acc[24][4] = {};
    int m0 = (wid >> 1)*32, n0 = (wid & 1)*96;
    wgemm<2,12>(sb,            sb + TILE_W*4,   Bbase,                Bbase + TILEQ_W*4,   m0, n0, lane, acc);
    wgemm<2,12>(sb + 2*TILE_W*4, sb + 3*TILE_W*4, Bbase + 2*TILEQ_W*4, Bbase + 3*TILEQ_W*4, m0, n0, lane, acc);
    __syncthreads();

    float* stage = (float*)smw;
#pragma unroll
    for (int mt = 0; mt < 2; mt++)
#pragma unroll
        for (int nt = 0; nt < 12; nt++) {
            int m = m0 + mt*16 + g, n = n0 + nt*8 + 2*tg;
            stage[n*132 + m]         = acc[mt*12+nt][0];
            stage[(n+1)*132 + m]     = acc[mt*12+nt][1];
            stage[n*132 + m + 8]     = acc[mt*12+nt][2];
            stage[(n+1)*132 + m + 8] = acc[mt*12+nt][3];
        }
    __syncthreads();

    float* qd = g_q + (size_t)b*2097152 + (size_t)h*128;
#pragma unroll
    for (int it = 0; it < 16; it++) {
        int idx = it*256 + tid;
        int c = idx >> 5, m4 = (idx & 31)*4;
        float bias = bq[c];
        float4 v = *(float4*)(stage + c*132 + m4);
        v.x += bias; v.y += bias; v.z += bias; v.w += bias;
        *(float4*)(qd + (size_t)c*16384 + m4) = v;
    }
    float* zd = g_z + (size_t)b*1048576 + (size_t)h*128;
#pragma unroll
    for (int it = 0; it < 7; it++) {
        int idx = it*256 + tid;
        if (idx < 1600) {
            int zr = idx >> 5, m4 = (idx & 31)*4;
            float4 v = *(float4*)(stage + (128 + zr)*132 + m4);
            *(float4*)(zd + (size_t)zr*16384 + m4) = v;
        }
    }
}

// ----------------- offset2 (unchanged) -----------------
__global__ void __launch_bounds__(256) offset2_kernel() {
    int p = blockIdx.x*256 + threadIdx.x;
    int b = p >> 14, rem = p & 16383;
    int h = rem >> 7, w = rem & 127;
    const float* zb = g_z + (size_t)b*1048576;
    float a0 = g_beff[0], a1 = g_beff[1];
#pragma unroll
    for (int kh = 0; kh < 5; kh++) {
        int hh = h + kh - 2;
        if ((unsigned)hh > 127u) continue;
#pragma unroll
        for (int kw = 0; kw < 5; kw++) {
            int ww = w + kw - 2;
            if ((unsigned)ww > 127u) continue;
            int t = kh*5 + kw, sp = hh*128 + ww;
            a0 += zb[(size_t)t*16384 + sp]        + g_zbias[t];
            a1 += zb[(size_t)(25 + t)*16384 + sp] + g_zbias[25 + t];
        }
    }
    float off0 = tanhf(a0)*5.f, off1 = tanhf(a1)*5.f;
    g_coords[2*p]     = ((float)w + off0)*(128.f/127.f) - 0.5f;
    g_coords[2*p + 1] = ((float)h + off1)*(128.f/127.f) - 0.5f;
}

// ----------------- merged k + vT projection (unchanged from R14) -----------------
__global__ void __launch_bounds__(256,2) pk_kernel(const float* __restrict__ bk,
                                                   const float* __restrict__ bv,
                                                   const float* __restrict__ rel) {
    extern __shared__ unsigned smw[];
    unsigned *Ah = smw, *Al = smw + TILE_W;
    unsigned sb = (unsigned)__cvta_generic_to_shared(smw);
    unsigned AhB = sb, AlB = sb + TILE_W*4;
    unsigned Bbase = sb + 2*TILE_W*4;
    int tid = threadIdx.x, wid = tid >> 5, lane = tid & 31;
    int g = lane >> 2, tg = lane & 3;
    int gb = blockIdx.x;
    int wsel = gb >> 9;
    int q = gb & 511;
    int b = q >> 7, q2 = q & 127;
    int blk_mul = wsel ? 128 : 16384;
    int row_mul = wsel ? 16384 : 128;
    const float* bias = wsel ? bv : bk;
    const float* src = g_xs + (size_t)b*2097152 + (size_t)q2*blk_mul;
    float* dst = wsel ? g_vT : g_k;

    prefetch_B2<TILE_W>(g_Wth[wsel][0], g_Wtl[wsel][0], g_Wth[wsel][1], g_Wtl[wsel][1],
                        Bbase, tid);

    float acc[16][4] = {};
    int m0 = (wid >> 1)*32, n0 = (wid & 1)*64;

    fill_chunkR<128>(src, row_mul, 0, 1.f, Ah, Al, tid);
    cpa_wait0();
    __syncthreads();
    wgemm<2,8>(AhB, AlB, Bbase, Bbase + TILE_W*4, m0, n0, lane, acc);
    __syncthreads();
    fill_chunkR<128>(src, row_mul, 1, 1.f, Ah, Al, tid);
    __syncthreads();
    wgemm<2,8>(AhB, AlB, Bbase + 2*TILE_W*4, Bbase + 3*TILE_W*4, m0, n0, lane, acc);
    __syncthreads();

    float* stage = (float*)smw;
#pragma unroll
    for (int mt = 0; mt < 2; mt++)
#pragma unroll
        for (int nt = 0; nt < 8; nt++) {
            int m = m0 + mt*16 + g, n = n0 + nt*8 + 2*tg;
            stage[n*132 + m]         = acc[mt*8+nt][0];
            stage[(n+1)*132 + m]     = acc[mt*8+nt][1];
            stage[n*132 + m + 8]     = acc[mt*8+nt][2];
            stage[(n+1)*132 + m + 8] = acc[mt*8+nt][3];
        }
    __syncthreads();

    float* db = dst + (size_t)b*2097152 + (size_t)q2*128;
#pragma unroll
    for (int it = 0; it < 16; it++) {
        int idx = it*256 + tid;
        int c = idx >> 5, m4 = (idx & 31)*4;
        float bc = bias[c];
        float4 v = *(float4*)(stage + c*132 + m4);
        if (wsel) {
            float4 rv = *(const float4*)(rel + c*128 + m4);
            v.x += bc + rv.x; v.y += bc + rv.y; v.z += bc + rv.z; v.w += bc + rv.w;
        } else {
            v.x += bc; v.y += bc; v.z += bc; v.w += bc;
        }
        *(float4*)(db + (size_t)c*16384 + m4) = v;
    }
}

// ----------------- bilinear gather (unchanged) -----------------
__global__ void __launch_bounds__(256) sample_kernel(const float* __restrict__ x) {
    int tid = threadIdx.x;
    int lane = tid & 31, wa = tid >> 5;
    int b = blockIdx.x >> 7, h = blockIdx.x & 127;
    const float* xb = x + (size_t)b*2097152;
    for (int w = wa; w < 128; w += 8) {
        size_t p = ((size_t)(b*128 + h))*128 + w;
        float xg = g_coords[2*p], yg = g_coords[2*p + 1];
        float x0 = floorf(xg), y0 = floorf(yg);
        float4 out = make_float4(0.f, 0.f, 0.f, 0.f);
#pragma unroll
        for (int dy = 0; dy < 2; dy++)
#pragma unroll
            for (int dx = 0; dx < 2; dx++) {
                float xi = x0 + (float)dx, yi = y0 + (float)dy;
                float wt = (1.f - fabsf(xg - xi))*(1.f - fabsf(yg - yi));
                bool valid = (xi >= 0.f) && (xi <= 127.f) && (yi >= 0.f) && (yi <= 127.f);
                float wv = valid ? wt : 0.f;
                int ix = min(max((int)xi, 0), 127);
                int iy = min(max((int)yi, 0), 127);
                float4 src = *(const float4*)(xb + ((size_t)(iy*128 + ix))*128 + lane*4);
                out.x += wv*src.x; out.y += wv*src.y; out.z += wv*src.z; out.w += wv*src.w;
            }
        *(float4*)(g_xs + p*128 + lane*4) = out;
    }
}

// ----------------- attention: 12-tile pipeline, 5 barriers -----------------
__global__ void __launch_bounds__(256) attn_kernel(const float* __restrict__ bo,
                                                   float* __restrict__ out) {
    extern __shared__ unsigned smw[];
    unsigned *A0h = smw,            *A0l = smw + TILE_W;
    unsigned *A1h = smw + 2*TILE_W, *A1l = smw + 3*TILE_W;
    unsigned *Bk0h = smw + 4*TILE_W, *Bk0l = smw + 5*TILE_W;
    unsigned *Bk1h = smw + 6*TILE_W, *Bk1l = smw + 7*TILE_W;
    unsigned *Bv0h = smw + 8*TILE_W, *Bv0l = smw + 9*TILE_W;
    unsigned *Bv1h = smw + 10*TILE_W, *Bv1l = smw + 11*TILE_W;
    unsigned sb = (unsigned)__cvta_generic_to_shared(smw);
    unsigned A0 = sb, A1 = sb + 2*TILE_W*4;
    unsigned Bk = sb + 4*TILE_W*4, Bv = sb + 8*TILE_W*4;
    int tid = threadIdx.x, wid = tid >> 5, lane = tid & 31;
    int g = lane >> 2, tg = lane & 3;
    int s = blockIdx.x;
    const float* qs = g_q  + (size_t)s*16384;
    const float* ks = g_k  + (size_t)s*16384;
    const float* vs = g_vT + (size_t)s*16384;
    int m0 = wid*16;

    // ---- batch all six activation fills upfront ----
    fill_chunkR<128>(qs, 128, 0, ATT_SCALE, A0h, A0l, tid);
    fill_chunkR<128>(qs, 128, 1, ATT_SCALE, A1h, A1l, tid);
    fill_chunkR<128>(ks, 128, 0, 1.f, Bk0h, Bk0l, tid);
    fill_chunkR<128>(ks, 128, 1, 1.f, Bk1h, Bk1l, tid);
    fill_chunkR<128>(vs, 128, 0, 1.f, Bv0h, Bv0l, tid);
    fill_chunkR<128>(vs, 128, 1, 1.f, Bv1h, Bv1l, tid);
    __syncthreads();

    // ---- S = (q*scale) @ k^T, both chunks back-to-back ----
    float sacc[16][4] = {};
    wgemm<1,16>(A0, A0 + TILE_W*4, Bk, Bk + TILE_W*4, m0, 0, lane, sacc);
    wgemm<1,16>(A1, A1 + TILE_W*4, Bk + 2*TILE_W*4, Bk + 3*TILE_W*4, m0, 0, lane, sacc);
    __syncthreads();                         // A, Bk reads complete

    // ---- prefetch Wo into the dead Bk buffers (hidden under softmax + PV) ----
    prefetch_B2<TILE_W>(g_Wth[2][0], g_Wtl[2][0], g_Wth[2][1], g_Wtl[2][1], Bk, tid);

    // ---- softmax ----
    float mx0 = -1e30f, mx1 = -1e30f;
#pragma unroll
    for (int nt = 0; nt < 16; nt++) {
        mx0 = fmaxf(mx0, fmaxf(sacc[nt][0], sacc[nt][1]));
        mx1 = fmaxf(mx1, fmaxf(sacc[nt][2], sacc[nt][3]));
    }
    mx0 = fmaxf(mx0, __shfl_xor_sync(~0u, mx0, 1)); mx0 = fmaxf(mx0, __shfl_xor_sync(~0u, mx0, 2));
    mx1 = fmaxf(mx1, __shfl_xor_sync(~0u, mx1, 1)); mx1 = fmaxf(mx1, __shfl_xor_sync(~0u, mx1, 2));
    float s0 = 0.f, s1 = 0.f;
#pragma unroll
    for (int nt = 0; nt < 16; nt++) {
        sacc[nt][0] = __expf(sacc[nt][0] - mx0); s0 += sacc[nt][0];
        sacc[nt][1] = __expf(sacc[nt][1] - mx0); s0 += sacc[nt][1];
        sacc[nt][2] = __expf(sacc[nt][2] - mx1); s1 += sacc[nt][2];
        sacc[nt][3] = __expf(sacc[nt][3] - mx1); s1 += sacc[nt][3];
    }
    s0 += __shfl_xor_sync(~0u, s0, 1); s0 += __shfl_xor_sync(~0u, s0, 2);
    s1 += __shfl_xor_sync(~0u, s1, 1); s1 += __shfl_xor_sync(~0u, s1, 2);
    float inv0 = 1.f/s0, inv1 = 1.f/s1;

    // ---- P chunks into A0/A1 (each warp owns rows m0+g, m0+g+8) ----
#pragma unroll
    for (int nt = 0; nt < 16; nt++) {
        unsigned* Ph = (nt < 8) ? A0h : A1h;
        unsigned* Pl = (nt < 8) ? A0l : A1l;
        int wcol = (nt & 7)*4 + tg;
        float p0 = sacc[nt][0]*inv0, p1 = sacc[nt][1]*inv0;
        float p2 = sacc[nt][2]*inv1, p3 = sacc[nt][3]*inv1;
        unsigned h0 = packh(p0, p1), h1 = packh(p2, p3);
        int o0 = (m0 + g)*PW + wcol, o1 = (m0 + g + 8)*PW + wcol;
        Ph[o0] = h0; Pl[o0] = packl(p0, p1, h0);
        Ph[o1] = h1; Pl[o1] = packl(p2, p3, h1);
    }
    __syncthreads();

    // ---- PV = P @ vT^T, both chunks back-to-back ----
    float acc2[16][4] = {};
    wgemm<1,16>(A0, A0 + TILE_W*4, Bv, Bv + TILE_W*4, m0, 0, lane, acc2);
    wgemm<1,16>(A1, A1 + TILE_W*4, Bv + 2*TILE_W*4, Bv + 3*TILE_W*4, m0, 0, lane, acc2);
    __syncthreads();

    // ---- PV chunks into A0/A1 ----
#pragma unroll
    for (int nt = 0; nt < 16; nt++) {
        unsigned* Ph = (nt < 8) ? A0h : A1h;
        unsigned* Pl = (nt < 8) ? A0l : A1l;
        int wcol = (nt & 7)*4 + tg;
        float p0 = acc2[nt][0], p1 = acc2[nt][1];
        float p2 = acc2[nt][2], p3 = acc2[nt][3];
        unsigned h0 = packh(p0, p1), h1 = packh(p2, p3);
        int o0 = (m0 + g)*PW + wcol, o1 = (m0 + g + 8)*PW + wcol;
        Ph[o0] = h0; Pl[o0] = packl(p0, p1, h0);
        Ph[o1] = h1; Pl[o1] = packl(p2, p3, h1);
    }
    cpa_wait0();                             // Wo resident in Bk
    __syncthreads();

    // ---- O = PV @ Wo^T ----
    float acc3[16][4] = {};
    wgemm<1,16>(A0, A0 + TILE_W*4, Bk, Bk + TILE_W*4, m0, 0, lane, acc3);
    wgemm<1,16>(A1, A1 + TILE_W*4, Bk + 2*TILE_W*4, Bk + 3*TILE_W*4, m0, 0, lane, acc3);

    // ---- epilogue ----
    float* ob = out + (size_t)s*16384;
#pragma unroll
    for (int nt = 0; nt < 16; nt++) {
        int n = nt*8 + 2*tg, m = m0 + g;
        float b0 = bo[n], b1 = bo[n+1];
        *(float2*)(ob + (size_t)m*128 + n)     = make_float2(acc3[nt][0] + b0, acc3[nt][1] + b1);
        *(float2*)(ob + (size_t)(m+8)*128 + n) = make_float2(acc3[nt][2] + b0, acc3[nt][3] + b1);
    }
}

// ----------------- launch -----------------
extern "C" void kernel_launch(void* const* d_in, const int* in_sizes, int n_in,
                              void* d_out, int out_size) {
    const float* x   = (const float*)d_in[0];
    const float* Wq  = (const float*)d_in[2];
    const float* bq  = (const float*)d_in[3];
    const float* Wk  = (const float*)d_in[4];
    const float* bk  = (const float*)d_in[5];
    const float* Wv  = (const float*)d_in[6];
    const float* bv  = (const float*)d_in[7];
    const float* Wo  = (const float*)d_in[8];
    const float* bo  = (const float*)d_in[9];
    const float* Wc1 = (const float*)d_in[10];
    const float* bc1 = (const float*)d_in[11];
    const float* Wc2 = (const float*)d_in[12];
    const float* rb  = (const float*)d_in[13];
    float* out = (float*)d_out;

    cudaFuncSetAttribute(qproj_kernel, cudaFuncAttributeMaxDynamicSharedMemorySize, SMEM_Q);
    cudaFuncSetAttribute(pk_kernel,    cudaFuncAttributeMaxDynamicSharedMemorySize, SMEM_PK);
    cudaFuncSetAttribute(attn_kernel,  cudaFuncAttributeMaxDynamicSharedMemorySize, SMEM_ATT);

    prep_kernel   <<<51,   256>>>(Wq, Wc1, Wc2, bc1);
    prep2_kernel  <<<50,   128>>>(Wq, bq);
    prepW_kernel  <<<8,    256>>>(Wk, Wv, Wo);
    qproj_kernel  <<<512,  256, SMEM_Q>>>(x, bq);
    offset2_kernel<<<256,  256>>>();
    sample_kernel <<<512,  256>>>(x);
    pk_kernel     <<<1024, 256, SMEM_PK>>>(bk, bv, rb);
    attn_kernel   <<<512,  256, SMEM_ATT>>>(bo, out);
}

// round 16
// speedup vs baseline: 1.3153x; 1.0408x over previous
#include <cuda_runtime.h>
#include <math.h>
#include <stdint.h>

#define ATT_SCALE 0.08838834764831845f   // 128^-0.5
#define PW 36                            // u32-word pitch of bf16 tiles (4 mod 32 -> conflict-free)

#define TILE_W  (128*PW)                 // 4608 words per 128-row tile
#define TILEQ_W (192*PW)                 // 6912 words per 192-row tile
#define TILH_W  (96*PW)                  // 3456 words per 96-row sub-tile
#define SMEM_ATT 221184                  // attn: 12 x 128-row tiles
#define SMEM_PK  110592                  // pk: A pair + 2 chunk B pairs
#define SMEM_Q2  92160                   // qproj: A pair (36864) + 4 x 96-row B tiles (55296)

// ----------------- scratch (device globals; only referenced from device code) -----------------
__device__ __align__(128) float g_q  [4*128*16384];   // (B,C,H,W)
__device__ __align__(128) float g_k  [4*128*16384];   // (B,C,H,W)
__device__ __align__(128) float g_vT [4*128*16384];   // (B,C,W,H)
__device__ __align__(128) float g_xs [65536*128];     // (B,H,W,C)
__device__ __align__(128) float g_z  [4*64*16384];    // 50 offset-tap projections per batch
__device__ __align__(128) float g_coords[65536*2];
__device__ __align__(128) float g_Weff[50*128];
__device__ __align__(128) float g_zbias[50];
__device__ __align__(128) float g_beff[2];
__device__ __align__(128) float g_Wqz[192*128];
__device__ __align__(128) unsigned g_WthQ[2][TILEQ_W];
__device__ __align__(128) unsigned g_WtlQ[2][TILEQ_W];
__device__ __align__(128) unsigned g_Wth[3][2][TILE_W];   // 0=Wk, 1=Wv, 2=Wo
__device__ __align__(128) unsigned g_Wtl[3][2][TILE_W];

// ----------------- helpers -----------------
static __device__ __forceinline__ void mmabf(float c[4], const unsigned a[4],
                                             unsigned b0, unsigned b1) {
    asm volatile("mma.sync.aligned.m16n8k16.row.col.f32.bf16.bf16.f32 "
        "{%0,%1,%2,%3},{%4,%5,%6,%7},{%8,%9},{%0,%1,%2,%3};"
        : "+f"(c[0]), "+f"(c[1]), "+f"(c[2]), "+f"(c[3])
        : "r"(a[0]), "r"(a[1]), "r"(a[2]), "r"(a[3]), "r"(b0), "r"(b1));
}
static __device__ __forceinline__ void ldsm4(unsigned r[4], unsigned addr) {
    asm volatile("ldmatrix.sync.aligned.m8n8.x4.shared.b16 {%0,%1,%2,%3},[%4];"
        : "=r"(r[0]), "=r"(r[1]), "=r"(r[2]), "=r"(r[3]) : "r"(addr));
}
static __device__ __forceinline__ unsigned packh(float x0, float x1) {
    unsigned h; asm("cvt.rn.bf16x2.f32 %0,%1,%2;" : "=r"(h) : "f"(x1), "f"(x0)); return h;
}
static __device__ __forceinline__ unsigned packl(float x0, float x1, unsigned h) {
    float h0 = __uint_as_float(h << 16), h1 = __uint_as_float(h & 0xffff0000u);
    return packh(x0 - h0, x1 - h1);
}
static __device__ __forceinline__ void cpa16(unsigned dst, const void* src) {
    asm volatile("cp.async.cg.shared.global [%0], [%1], 16;" :: "r"(dst), "l"(src));
}
static __device__ __forceinline__ void cpa_commit() {
    asm volatile("cp.async.commit_group;" ::: "memory");
}
static __device__ __forceinline__ void cpa_wait0() {
    asm volatile("cp.async.wait_group 0;" ::: "memory");
}

// load a ROWSx64 fp32 chunk (cols kc*64..) into hi/lo bf16-pair word tiles; 256 threads
template<int ROWS>
static __device__ __forceinline__ void fill_chunkR(const float* __restrict__ src, int ld, int kc,
                                                   float scale, unsigned* th, unsigned* tl, int tid) {
#pragma unroll
    for (int it = 0; it < ROWS/16; it++) {
        int idx = it*256 + tid;
        int r = idx >> 4, c4 = (idx & 15)*4;
        float4 v = *(const float4*)(src + (size_t)r*ld + kc*64 + c4);
        float x0 = v.x*scale, x1 = v.y*scale, x2 = v.z*scale, x3 = v.w*scale;
        unsigned h0 = packh(x0, x1), h1 = packh(x2, x3);
        unsigned l0 = packl(x0, x1, h0), l1 = packl(x2, x3, h1);
        int o = r*PW + (c4 >> 1);
        th[o] = h0; th[o+1] = h1;
        tl[o] = l0; tl[o+1] = l1;
    }
}

// async prefetch of 4 tiles of NW words (hi0, lo0, hi1, lo1) into consecutive smem; 256 threads
template<int NW>
static __device__ __forceinline__ void prefetch_B2(const unsigned* __restrict__ h0,
                                                   const unsigned* __restrict__ l0,
                                                   const unsigned* __restrict__ h1,
                                                   const unsigned* __restrict__ l1,
                                                   unsigned dstb, int tid) {
    const unsigned* srcs[4] = {h0, l0, h1, l1};
    const int NV = NW/4;
#pragma unroll
    for (int it = 0; it < (4*NV + 255)/256; it++) {
        int idx = it*256 + tid;
        if (idx < 4*NV) {
            int t = idx / NV, off = idx - t*NV;
            cpa16(dstb + (unsigned)(t*NW + off*4)*4u, srcs[t] + (size_t)off*4);
        }
    }
    cpa_commit();
}

// warp GEMM over one K=64 chunk via ldmatrix: C[m0..+MT*16][n0..+NT*8] += A @ B^T (bf16x3)
template<int MT, int NT>
static __device__ __forceinline__ void wgemm(unsigned AhB, unsigned AlB,
                                             unsigned BhB, unsigned BlB,
                                             int m0, int n0, int lane, float (*acc)[4]) {
    unsigned aoff = ((m0 + ((lane>>3)&1)*8 + (lane&7))*PW + ((lane>>4)<<2))*4;
    unsigned boff = ((n0 + (lane>>4)*8 + (lane&7))*PW + (((lane>>3)&1)<<2))*4;
#pragma unroll
    for (int ks = 0; ks < 4; ks++) {
        unsigned ka = ks*32;
        unsigned ah[MT][4], al[MT][4];
#pragma unroll
        for (int mt = 0; mt < MT; mt++) {
            ldsm4(ah[mt], AhB + aoff + mt*(16*PW*4) + ka);
            ldsm4(al[mt], AlB + aoff + mt*(16*PW*4) + ka);
        }
#pragma unroll
        for (int ntp = 0; ntp < NT/2; ntp++) {
            unsigned bh[4], bl[4];
            unsigned bo = boff + ntp*(16*PW*4) + ka;
            ldsm4(bh, BhB + bo);
            ldsm4(bl, BlB + bo);
#pragma unroll
            for (int mt = 0; mt < MT; mt++) {
                float* c0 = acc[mt*NT + 2*ntp];
                float* c1 = acc[mt*NT + 2*ntp + 1];
                mmabf(c0, ah[mt], bh[0], bh[1]);
                mmabf(c0, ah[mt], bl[0], bl[1]);
                mmabf(c0, al[mt], bh[0], bh[1]);
                mmabf(c1, ah[mt], bh[2], bh[3]);
                mmabf(c1, ah[mt], bl[2], bl[3]);
                mmabf(c1, al[mt], bh[2], bh[3]);
            }
        }
    }
}

// ----------------- prep kernels (unchanged) -----------------
__global__ void prep_kernel(const float* __restrict__ Wq, const float* __restrict__ Wc1,
                            const float* __restrict__ Wc2, const float* __restrict__ bc1) {
    int blk = blockIdx.x, tid = threadIdx.x;
    if (blk < 50) {
        int j = blk / 25, t = blk % 25;
        if (tid < 128) {
            float s = 0.f;
            for (int o = 0; o < 128; o++)
                s += Wc2[j*128 + o] * Wc1[((size_t)(o*128 + tid))*25 + t];
            g_Weff[blk*128 + tid] = s;
        }
    } else {
        for (int i = tid; i < 16384; i += 256) g_Wqz[i] = Wq[i];
        for (int i = tid; i < 14*128; i += 256) g_Wqz[178*128 + i] = 0.f;
        if (tid < 2) {
            float s = 0.f;
            for (int o = 0; o < 128; o++) s += Wc2[tid*128 + o] * bc1[o];
            g_beff[tid] = s;
        }
    }
}
__global__ void prep2_kernel(const float* __restrict__ Wq, const float* __restrict__ bq) {
    int jt = blockIdx.x, tid = threadIdx.x;
    float s = 0.f;
    for (int c = 0; c < 128; c++) s += g_Weff[jt*128 + c] * Wq[c*128 + tid];
    g_Wqz[(128 + jt)*128 + tid] = s;
    if (tid == 0) {
        float z = 0.f;
        for (int c = 0; c < 128; c++) z += g_Weff[jt*128 + c] * bq[c];
        g_zbias[jt] = z;
    }
}
__global__ void prepW_kernel(const float* __restrict__ Wk, const float* __restrict__ Wv,
                             const float* __restrict__ Wo) {
    int blk = blockIdx.x, tid = threadIdx.x;
    if (blk < 2) {
        fill_chunkR<192>(g_Wqz, 128, blk, 1.f, g_WthQ[blk], g_WtlQ[blk], tid);
    } else {
        int w = (blk - 2) >> 1, kc = (blk - 2) & 1;
        const float* W = (w == 0) ? Wk : (w == 1) ? Wv : Wo;
        fill_chunkR<128>(W, 128, kc, 1.f, g_Wth[w][kc], g_Wtl[w][kc], tid);
    }
}

// ----------------- qproj: N split across 2 blocks (96 each), 2 CTAs/SM -----------------
__global__ void __launch_bounds__(256,2) qproj_kernel(const float* __restrict__ x,
                                                      const float* __restrict__ bq) {
    extern __shared__ unsigned smw[];
    unsigned *Ah = smw, *Al = smw + TILE_W;
    unsigned sb = (unsigned)__cvta_generic_to_shared(smw);
    unsigned AhB = sb, AlB = sb + TILE_W*4;
    unsigned Bbase = sb + 2*TILE_W*4;          // 4 x 96-row tiles: h0,l0,h1,l1
    int tid = threadIdx.x, wid = tid >> 5, lane = tid & 31;
    int g = lane >> 2, tg = lane & 3;
    int nh = blockIdx.x >> 9;                  // n-half: rows nh*96 .. nh*96+95 of Wqz
    int q = blockIdx.x & 511;
    int b = q >> 7, h = q & 127;
    const float* src = x + (size_t)b*2097152 + (size_t)h*16384;
    int rowoff = nh*TILH_W;                    // word offset of 96-row sub-tile

    prefetch_B2<TILH_W>(g_WthQ[0] + rowoff, g_WtlQ[0] + rowoff,
                        g_WthQ[1] + rowoff, g_WtlQ[1] + rowoff, Bbase, tid);

    float acc[12][4] = {};
    int m0 = (wid >> 1)*32, n0 = (wid & 1)*48;

    fill_chunkR<128>(src, 128, 0, 1.f, Ah, Al, tid);
    cpa_wait0();
    __syncthreads();
    wgemm<2,6>(AhB, AlB, Bbase, Bbase + TILH_W*4, m0, n0, lane, acc);
    __syncthreads();
    fill_chunkR<128>(src, 128, 1, 1.f, Ah, Al, tid);
    __syncthreads();
    wgemm<2,6>(AhB, AlB, Bbase + 2*TILH_W*4, Bbase + 3*TILH_W*4, m0, n0, lane, acc);
    __syncthreads();

    // stage transposed [ln][m], pitch 132, 96 local rows
    float* stage = (float*)smw;
#pragma unroll
    for (int mt = 0; mt < 2; mt++)
#pragma unroll
        for (int nt = 0; nt < 6; nt++) {
            int m = m0 + mt*16 + g, n = n0 + nt*8 + 2*tg;
            stage[n*132 + m]         = acc[mt*6+nt][0];
            stage[(n+1)*132 + m]     = acc[mt*6+nt][1];
            stage[n*132 + m + 8]     = acc[mt*6+nt][2];
            stage[(n+1)*132 + m + 8] = acc[mt*6+nt][3];
        }
    __syncthreads();

    // outputs: global row gn = nh*96 + ln;  gn<128 -> q channel, 128<=gn<178 -> z tap
    float* qd = g_q + (size_t)b*2097152 + (size_t)h*128;
    float* zd = g_z + (size_t)b*1048576 + (size_t)h*128;
#pragma unroll
    for (int it = 0; it < 12; it++) {
        int idx = it*256 + tid;                // 96 rows x 32 float4 = 3072
        int ln = idx >> 5, m4 = (idx & 31)*4;
        int gn = nh*96 + ln;
        float4 v = *(float4*)(stage + ln*132 + m4);
        if (gn < 128) {
            float bias = bq[gn];
            v.x += bias; v.y += bias; v.z += bias; v.w += bias;
            *(float4*)(qd + (size_t)gn*16384 + m4) = v;
        } else if (gn < 178) {
            *(float4*)(zd + (size_t)(gn - 128)*16384 + m4) = v;
        }
    }
}

// ----------------- offset2 (unchanged) -----------------
__global__ void __launch_bounds__(256) offset2_kernel() {
    int p = blockIdx.x*256 + threadIdx.x;
    int b = p >> 14, rem = p & 16383;
    int h = rem >> 7, w = rem & 127;
    const float* zb = g_z + (size_t)b*1048576;
    float a0 = g_beff[0], a1 = g_beff[1];
#pragma unroll
    for (int kh = 0; kh < 5; kh++) {
        int hh = h + kh - 2;
        if ((unsigned)hh > 127u) continue;
#pragma unroll
        for (int kw = 0; kw < 5; kw++) {
            int ww = w + kw - 2;
            if ((unsigned)ww > 127u) continue;
            int t = kh*5 + kw, sp = hh*128 + ww;
            a0 += zb[(size_t)t*16384 + sp]        + g_zbias[t];
            a1 += zb[(size_t)(25 + t)*16384 + sp] + g_zbias[25 + t];
        }
    }
    float off0 = tanhf(a0)*5.f, off1 = tanhf(a1)*5.f;
    g_coords[2*p]     = ((float)w + off0)*(128.f/127.f) - 0.5f;
    g_coords[2*p + 1] = ((float)h + off1)*(128.f/127.f) - 0.5f;
}

// ----------------- merged k + vT projection (unchanged from R15) -----------------
__global__ void __launch_bounds__(256,2) pk_kernel(const float* __restrict__ bk,
                                                   const float* __restrict__ bv,
                                                   const float* __restrict__ rel) {
    extern __shared__ unsigned smw[];
    unsigned *Ah = smw, *Al = smw + TILE_W;
    unsigned sb = (unsigned)__cvta_generic_to_shared(smw);
    unsigned AhB = sb, AlB = sb + TILE_W*4;
    unsigned Bbase = sb + 2*TILE_W*4;
    int tid = threadIdx.x, wid = tid >> 5, lane = tid & 31;
    int g = lane >> 2, tg = lane & 3;
    int gb = blockIdx.x;
    int wsel = gb >> 9;
    int q = gb & 511;
    int b = q >> 7, q2 = q & 127;
    int blk_mul = wsel ? 128 : 16384;
    int row_mul = wsel ? 16384 : 128;
    const float* bias = wsel ? bv : bk;
    const float* src = g_xs + (size_t)b*2097152 + (size_t)q2*blk_mul;
    float* dst = wsel ? g_vT : g_k;

    prefetch_B2<TILE_W>(g_Wth[wsel][0], g_Wtl[wsel][0], g_Wth[wsel][1], g_Wtl[wsel][1],
                        Bbase, tid);

    float acc[16][4] = {};
    int m0 = (wid >> 1)*32, n0 = (wid & 1)*64;

    fill_chunkR<128>(src, row_mul, 0, 1.f, Ah, Al, tid);
    cpa_wait0();
    __syncthreads();
    wgemm<2,8>(AhB, AlB, Bbase, Bbase + TILE_W*4, m0, n0, lane, acc);
    __syncthreads();
    fill_chunkR<128>(src, row_mul, 1, 1.f, Ah, Al, tid);
    __syncthreads();
    wgemm<2,8>(AhB, AlB, Bbase + 2*TILE_W*4, Bbase + 3*TILE_W*4, m0, n0, lane, acc);
    __syncthreads();

    float* stage = (float*)smw;
#pragma unroll
    for (int mt = 0; mt < 2; mt++)
#pragma unroll
        for (int nt = 0; nt < 8; nt++) {
            int m = m0 + mt*16 + g, n = n0 + nt*8 + 2*tg;
            stage[n*132 + m]         = acc[mt*8+nt][0];
            stage[(n+1)*132 + m]     = acc[mt*8+nt][1];
            stage[n*132 + m + 8]     = acc[mt*8+nt][2];
            stage[(n+1)*132 + m + 8] = acc[mt*8+nt][3];
        }
    __syncthreads();

    float* db = dst + (size_t)b*2097152 + (size_t)q2*128;
#pragma unroll
    for (int it = 0; it < 16; it++) {
        int idx = it*256 + tid;
        int c = idx >> 5, m4 = (idx & 31)*4;
        float bc = bias[c];
        float4 v = *(float4*)(stage + c*132 + m4);
        if (wsel) {
            float4 rv = *(const float4*)(rel + c*128 + m4);
            v.x += bc + rv.x; v.y += bc + rv.y; v.z += bc + rv.z; v.w += bc + rv.w;
        } else {
            v.x += bc; v.y += bc; v.z += bc; v.w += bc;
        }
        *(float4*)(db + (size_t)c*16384 + m4) = v;
    }
}

// ----------------- bilinear gather (unchanged) -----------------
__global__ void __launch_bounds__(256) sample_kernel(const float* __restrict__ x) {
    int tid = threadIdx.x;
    int lane = tid & 31, wa = tid >> 5;
    int b = blockIdx.x >> 7, h = blockIdx.x & 127;
    const float* xb = x + (size_t)b*2097152;
    for (int w = wa; w < 128; w += 8) {
        size_t p = ((size_t)(b*128 + h))*128 + w;
        float xg = g_coords[2*p], yg = g_coords[2*p + 1];
        float x0 = floorf(xg), y0 = floorf(yg);
        float4 out = make_float4(0.f, 0.f, 0.f, 0.f);
#pragma unroll
        for (int dy = 0; dy < 2; dy++)
#pragma unroll
            for (int dx = 0; dx < 2; dx++) {
                float xi = x0 + (float)dx, yi = y0 + (float)dy;
                float wt = (1.f - fabsf(xg - xi))*(1.f - fabsf(yg - yi));
                bool valid = (xi >= 0.f) && (xi <= 127.f) && (yi >= 0.f) && (yi <= 127.f);
                float wv = valid ? wt : 0.f;
                int ix = min(max((int)xi, 0), 127);
                int iy = min(max((int)yi, 0), 127);
                float4 src = *(const float4*)(xb + ((size_t)(iy*128 + ix))*128 + lane*4);
                out.x += wv*src.x; out.y += wv*src.y; out.z += wv*src.z; out.w += wv*src.w;
            }
        *(float4*)(g_xs + p*128 + lane*4) = out;
    }
}

// ----------------- attention: 12-tile pipeline, 5 barriers (unchanged from R15) ----------
__global__ void __launch_bounds__(256) attn_kernel(const float* __restrict__ bo,
                                                   float* __restrict__ out) {
    extern __shared__ unsigned smw[];
    unsigned *A0h = smw,            *A0l = smw + TILE_W;
    unsigned *A1h = smw + 2*TILE_W, *A1l = smw + 3*TILE_W;
    unsigned *Bk0h = smw + 4*TILE_W, *Bk0l = smw + 5*TILE_W;
    unsigned *Bk1h = smw + 6*TILE_W, *Bk1l = smw + 7*TILE_W;
    unsigned *Bv0h = smw + 8*TILE_W, *Bv0l = smw + 9*TILE_W;
    unsigned *Bv1h = smw + 10*TILE_W, *Bv1l = smw + 11*TILE_W;
    unsigned sb = (unsigned)__cvta_generic_to_shared(smw);
    unsigned A0 = sb, A1 = sb + 2*TILE_W*4;
    unsigned Bk = sb + 4*TILE_W*4, Bv = sb + 8*TILE_W*4;
    int tid = threadIdx.x, wid = tid >> 5, lane = tid & 31;
    int g = lane >> 2, tg = lane & 3;
    int s = blockIdx.x;
    const float* qs = g_q  + (size_t)s*16384;
    const float* ks = g_k  + (size_t)s*16384;
    const float* vs = g_vT + (size_t)s*16384;
    int m0 = wid*16;

    fill_chunkR<128>(qs, 128, 0, ATT_SCALE, A0h, A0l, tid);
    fill_chunkR<128>(qs, 128, 1, ATT_SCALE, A1h, A1l, tid);
    fill_chunkR<128>(ks, 128, 0, 1.f, Bk0h, Bk0l, tid);
    fill_chunkR<128>(ks, 128, 1, 1.f, Bk1h, Bk1l, tid);
    fill_chunkR<128>(vs, 128, 0, 1.f, Bv0h, Bv0l, tid);
    fill_chunkR<128>(vs, 128, 1, 1.f, Bv1h, Bv1l, tid);
    __syncthreads();

    float sacc[16][4] = {};
    wgemm<1,16>(A0, A0 + TILE_W*4, Bk, Bk + TILE_W*4, m0, 0, lane, sacc);
    wgemm<1,16>(A1, A1 + TILE_W*4, Bk + 2*TILE_W*4, Bk + 3*TILE_W*4, m0, 0, lane, sacc);
    __syncthreads();

    prefetch_B2<TILE_W>(g_Wth[2][0], g_Wtl[2][0], g_Wth[2][1], g_Wtl[2][1], Bk, tid);

    float mx0 = -1e30f, mx1 = -1e30f;
#pragma unroll
    for (int nt = 0; nt < 16; nt++) {
        mx0 = fmaxf(mx0, fmaxf(sacc[nt][0], sacc[nt][1]));
        mx1 = fmaxf(mx1, fmaxf(sacc[nt][2], sacc[nt][3]));
    }
    mx0 = fmaxf(mx0, __shfl_xor_sync(~0u, mx0, 1)); mx0 = fmaxf(mx0, __shfl_xor_sync(~0u, mx0, 2));
    mx1 = fmaxf(mx1, __shfl_xor_sync(~0u, mx1, 1)); mx1 = fmaxf(mx1, __shfl_xor_sync(~0u, mx1, 2));
    float s0 = 0.f, s1 = 0.f;
#pragma unroll
    for (int nt = 0; nt < 16; nt++) {
        sacc[nt][0] = __expf(sacc[nt][0] - mx0); s0 += sacc[nt][0];
        sacc[nt][1] = __expf(sacc[nt][1] - mx0); s0 += sacc[nt][1];
        sacc[nt][2] = __expf(sacc[nt][2] - mx1); s1 += sacc[nt][2];
        sacc[nt][3] = __expf(sacc[nt][3] - mx1); s1 += sacc[nt][3];
    }
    s0 += __shfl_xor_sync(~0u, s0, 1); s0 += __shfl_xor_sync(~0u, s0, 2);
    s1 += __shfl_xor_sync(~0u, s1, 1); s1 += __shfl_xor_sync(~0u, s1, 2);
    float inv0 = 1.f/s0, inv1 = 1.f/s1;

#pragma unroll
    for (int nt = 0; nt < 16; nt++) {
        unsigned* Ph = (nt < 8) ? A0h : A1h;
        unsigned* Pl = (nt < 8) ? A0l : A1l;
        int wcol = (nt & 7)*4 + tg;
        float p0 = sacc[nt][0]*inv0, p1 = sacc[nt][1]*inv0;
        float p2 = sacc[nt][2]*inv1, p3 = sacc[nt][3]*inv1;
        unsigned h0 = packh(p0, p1), h1 = packh(p2, p3);
        int o0 = (m0 + g)*PW + wcol, o1 = (m0 + g + 8)*PW + wcol;
        Ph[o0] = h0; Pl[o0] = packl(p0, p1, h0);
        Ph[o1] = h1; Pl[o1] = packl(p2, p3, h1);
    }
    __syncthreads();

    float acc2[16][4] = {};
    wgemm<1,16>(A0, A0 + TILE_W*4, Bv, Bv + TILE_W*4, m0, 0, lane, acc2);
    wgemm<1,16>(A1, A1 + TILE_W*4, Bv + 2*TILE_W*4, Bv + 3*TILE_W*4, m0, 0, lane, acc2);
    __syncthreads();

#pragma unroll
    for (int nt = 0; nt < 16; nt++) {
        unsigned* Ph = (nt < 8) ? A0h : A1h;
        unsigned* Pl = (nt < 8) ? A0l : A1l;
        int wcol = (nt & 7)*4 + tg;
        float p0 = acc2[nt][0], p1 = acc2[nt][1];
        float p2 = acc2[nt][2], p3 = acc2[nt][3];
        unsigned h0 = packh(p0, p1), h1 = packh(p2, p3);
        int o0 = (m0 + g)*PW + wcol, o1 = (m0 + g + 8)*PW + wcol;
        Ph[o0] = h0; Pl[o0] = packl(p0, p1, h0);
        Ph[o1] = h1; Pl[o1] = packl(p2, p3, h1);
    }
    cpa_wait0();
    __syncthreads();

    float acc3[16][4] = {};
    wgemm<1,16>(A0, A0 + TILE_W*4, Bk, Bk + TILE_W*4, m0, 0, lane, acc3);
    wgemm<1,16>(A1, A1 + TILE_W*4, Bk + 2*TILE_W*4, Bk + 3*TILE_W*4, m0, 0, lane, acc3);

    float* ob = out + (size_t)s*16384;
#pragma unroll
    for (int nt = 0; nt < 16; nt++) {
        int n = nt*8 + 2*tg, m = m0 + g;
        float b0 = bo[n], b1 = bo[n+1];
        *(float2*)(ob + (size_t)m*128 + n)     = make_float2(acc3[nt][0] + b0, acc3[nt][1] + b1);
        *(float2*)(ob + (size_t)(m+8)*128 + n) = make_float2(acc3[nt][2] + b0, acc3[nt][3] + b1);
    }
}

// ----------------- launch -----------------
extern "C" void kernel_launch(void* const* d_in, const int* in_sizes, int n_in,
                              void* d_out, int out_size) {
    const float* x   = (const float*)d_in[0];
    const float* Wq  = (const float*)d_in[2];
    const float* bq  = (const float*)d_in[3];
    const float* Wk  = (const float*)d_in[4];
    const float* bk  = (const float*)d_in[5];
    const float* Wv  = (const float*)d_in[6];
    const float* bv  = (const float*)d_in[7];
    const float* Wo  = (const float*)d_in[8];
    const float* bo  = (const float*)d_in[9];
    const float* Wc1 = (const float*)d_in[10];
    const float* bc1 = (const float*)d_in[11];
    const float* Wc2 = (const float*)d_in[12];
    const float* rb  = (const float*)d_in[13];
    float* out = (float*)d_out;

    cudaFuncSetAttribute(qproj_kernel, cudaFuncAttributeMaxDynamicSharedMemorySize, SMEM_Q2);
    cudaFuncSetAttribute(pk_kernel,    cudaFuncAttributeMaxDynamicSharedMemorySize, SMEM_PK);
    cudaFuncSetAttribute(attn_kernel,  cudaFuncAttributeMaxDynamicSharedMemorySize, SMEM_ATT);

    prep_kernel   <<<51,   256>>>(Wq, Wc1, Wc2, bc1);
    prep2_kernel  <<<50,   128>>>(Wq, bq);
    prepW_kernel  <<<8,    256>>>(Wk, Wv, Wo);
    qproj_kernel  <<<1024, 256, SMEM_Q2>>>(x, bq);
    offset2_kernel<<<256,  256>>>();
    sample_kernel <<<512,  256>>>(x);
    pk_kernel     <<<1024, 256, SMEM_PK>>>(bk, bv, rb);
    attn_kernel   <<<512,  256, SMEM_ATT>>>(bo, out);
}

// round 17
// speedup vs baseline: 1.3889x; 1.0559x over previous
#include <cuda_runtime.h>
#include <math.h>
#include <stdint.h>

#define ATT_SCALE 0.08838834764831845f   // 128^-0.5
#define PW 36                            // u32-word pitch of bf16 tiles (4 mod 32 -> conflict-free)

#define TILE_W  (128*PW)                 // 4608 words per 128-row tile
#define TILEQ_W (192*PW)                 // 6912 words per 192-row tile
#define TILH_W  (96*PW)                  // 3456 words per 96-row sub-tile
#define SMEM_ATT 73728                   // attn: 4 x 128-row tiles (2 CTAs/SM)
#define SMEM_PK  110592                  // pk: A pair + 2 chunk B pairs
#define SMEM_Q2  92160                   // qproj: A pair + 4 x 96-row B tiles

// ----------------- scratch (device globals; only referenced from device code) -----------------
__device__ __align__(128) float g_q  [4*128*16384];   // (B,C,H,W)
__device__ __align__(128) float g_k  [4*128*16384];   // (B,C,H,W)
__device__ __align__(128) float g_vT [4*128*16384];   // (B,C,W,H)
__device__ __align__(128) float g_xs [65536*128];     // (B,H,W,C)
__device__ __align__(128) float g_z  [4*64*16384];    // 50 offset-tap projections per batch
__device__ __align__(128) float g_coords[65536*2];
__device__ __align__(128) float g_Weff[50*128];
__device__ __align__(128) float g_zbias[50];
__device__ __align__(128) float g_beff[2];
__device__ __align__(128) float g_Wqz[192*128];
__device__ __align__(128) unsigned g_WthQ[2][TILEQ_W];
__device__ __align__(128) unsigned g_WtlQ[2][TILEQ_W];
__device__ __align__(128) unsigned g_Wth[3][2][TILE_W];   // 0=Wk, 1=Wv, 2=Wo
__device__ __align__(128) unsigned g_Wtl[3][2][TILE_W];

// ----------------- helpers -----------------
static __device__ __forceinline__ void mmabf(float c[4], const unsigned a[4],
                                             unsigned b0, unsigned b1) {
    asm volatile("mma.sync.aligned.m16n8k16.row.col.f32.bf16.bf16.f32 "
        "{%0,%1,%2,%3},{%4,%5,%6,%7},{%8,%9},{%0,%1,%2,%3};"
        : "+f"(c[0]), "+f"(c[1]), "+f"(c[2]), "+f"(c[3])
        : "r"(a[0]), "r"(a[1]), "r"(a[2]), "r"(a[3]), "r"(b0), "r"(b1));
}
static __device__ __forceinline__ void ldsm4(unsigned r[4], unsigned addr) {
    asm volatile("ldmatrix.sync.aligned.m8n8.x4.shared.b16 {%0,%1,%2,%3},[%4];"
        : "=r"(r[0]), "=r"(r[1]), "=r"(r[2]), "=r"(r[3]) : "r"(addr));
}
static __device__ __forceinline__ unsigned packh(float x0, float x1) {
    unsigned h; asm("cvt.rn.bf16x2.f32 %0,%1,%2;" : "=r"(h) : "f"(x1), "f"(x0)); return h;
}
static __device__ __forceinline__ unsigned packl(float x0, float x1, unsigned h) {
    float h0 = __uint_as_float(h << 16), h1 = __uint_as_float(h & 0xffff0000u);
    return packh(x0 - h0, x1 - h1);
}
static __device__ __forceinline__ void cpa16(unsigned dst, const void* src) {
    asm volatile("cp.async.cg.shared.global [%0], [%1], 16;" :: "r"(dst), "l"(src));
}
static __device__ __forceinline__ void cpa_commit() {
    asm volatile("cp.async.commit_group;" ::: "memory");
}
static __device__ __forceinline__ void cpa_wait0() {
    asm volatile("cp.async.wait_group 0;" ::: "memory");
}

// load a ROWSx64 fp32 chunk (cols kc*64..) into hi/lo bf16-pair word tiles; 256 threads
template<int ROWS>
static __device__ __forceinline__ void fill_chunkR(const float* __restrict__ src, int ld, int kc,
                                                   float scale, unsigned* th, unsigned* tl, int tid) {
#pragma unroll
    for (int it = 0; it < ROWS/16; it++) {
        int idx = it*256 + tid;
        int r = idx >> 4, c4 = (idx & 15)*4;
        float4 v = *(const float4*)(src + (size_t)r*ld + kc*64 + c4);
        float x0 = v.x*scale, x1 = v.y*scale, x2 = v.z*scale, x3 = v.w*scale;
        unsigned h0 = packh(x0, x1), h1 = packh(x2, x3);
        unsigned l0 = packl(x0, x1, h0), l1 = packl(x2, x3, h1);
        int o = r*PW + (c4 >> 1);
        th[o] = h0; th[o+1] = h1;
        tl[o] = l0; tl[o+1] = l1;
    }
}

// copy a preconverted NW-word tile pair (global -> smem); 256 threads
template<int NW>
static __device__ __forceinline__ void copy_tileN(const unsigned* __restrict__ gh,
                                                  const unsigned* __restrict__ gl,
                                                  unsigned* th, unsigned* tl, int tid) {
#pragma unroll
    for (int it = 0; it < (NW/4 + 255)/256; it++) {
        int idx = it*256 + tid;
        if (idx < NW/4) {
            ((uint4*)th)[idx] = ((const uint4*)gh)[idx];
            ((uint4*)tl)[idx] = ((const uint4*)gl)[idx];
        }
    }
}

// async prefetch of 4 tiles of NW words (hi0, lo0, hi1, lo1) into consecutive smem; 256 threads
template<int NW>
static __device__ __forceinline__ void prefetch_B2(const unsigned* __restrict__ h0,
                                                   const unsigned* __restrict__ l0,
                                                   const unsigned* __restrict__ h1,
                                                   const unsigned* __restrict__ l1,
                                                   unsigned dstb, int tid) {
    const unsigned* srcs[4] = {h0, l0, h1, l1};
    const int NV = NW/4;
#pragma unroll
    for (int it = 0; it < (4*NV + 255)/256; it++) {
        int idx = it*256 + tid;
        if (idx < 4*NV) {
            int t = idx / NV, off = idx - t*NV;
            cpa16(dstb + (unsigned)(t*NW + off*4)*4u, srcs[t] + (size_t)off*4);
        }
    }
    cpa_commit();
}

// warp GEMM over one K=64 chunk via ldmatrix: C[m0..+MT*16][n0..+NT*8] += A @ B^T (bf16x3)
template<int MT, int NT>
static __device__ __forceinline__ void wgemm(unsigned AhB, unsigned AlB,
                                             unsigned BhB, unsigned BlB,
                                             int m0, int n0, int lane, float (*acc)[4]) {
    unsigned aoff = ((m0 + ((lane>>3)&1)*8 + (lane&7))*PW + ((lane>>4)<<2))*4;
    unsigned boff = ((n0 + (lane>>4)*8 + (lane&7))*PW + (((lane>>3)&1)<<2))*4;
#pragma unroll
    for (int ks = 0; ks < 4; ks++) {
        unsigned ka = ks*32;
        unsigned ah[MT][4], al[MT][4];
#pragma unroll
        for (int mt = 0; mt < MT; mt++) {
            ldsm4(ah[mt], AhB + aoff + mt*(16*PW*4) + ka);
            ldsm4(al[mt], AlB + aoff + mt*(16*PW*4) + ka);
        }
#pragma unroll
        for (int ntp = 0; ntp < NT/2; ntp++) {
            unsigned bh[4], bl[4];
            unsigned bo = boff + ntp*(16*PW*4) + ka;
            ldsm4(bh, BhB + bo);
            ldsm4(bl, BlB + bo);
#pragma unroll
            for (int mt = 0; mt < MT; mt++) {
                float* c0 = acc[mt*NT + 2*ntp];
                float* c1 = acc[mt*NT + 2*ntp + 1];
                mmabf(c0, ah[mt], bh[0], bh[1]);
                mmabf(c0, ah[mt], bl[0], bl[1]);
                mmabf(c0, al[mt], bh[0], bh[1]);
                mmabf(c1, ah[mt], bh[2], bh[3]);
                mmabf(c1, ah[mt], bl[2], bl[3]);
                mmabf(c1, al[mt], bh[2], bh[3]);
            }
        }
    }
}

// ----------------- prep kernels (unchanged) -----------------
__global__ void prep_kernel(const float* __restrict__ Wq, const float* __restrict__ Wc1,
                            const float* __restrict__ Wc2, const float* __restrict__ bc1) {
    int blk = blockIdx.x, tid = threadIdx.x;
    if (blk < 50) {
        int j = blk / 25, t = blk % 25;
        if (tid < 128) {
            float s = 0.f;
            for (int o = 0; o < 128; o++)
                s += Wc2[j*128 + o] * Wc1[((size_t)(o*128 + tid))*25 + t];
            g_Weff[blk*128 + tid] = s;
        }
    } else {
        for (int i = tid; i < 16384; i += 256) g_Wqz[i] = Wq[i];
        for (int i = tid; i < 14*128; i += 256) g_Wqz[178*128 + i] = 0.f;
        if (tid < 2) {
            float s = 0.f;
            for (int o = 0; o < 128; o++) s += Wc2[tid*128 + o] * bc1[o];
            g_beff[tid] = s;
        }
    }
}
__global__ void prep2_kernel(const float* __restrict__ Wq, const float* __restrict__ bq) {
    int jt = blockIdx.x, tid = threadIdx.x;
    float s = 0.f;
    for (int c = 0; c < 128; c++) s += g_Weff[jt*128 + c] * Wq[c*128 + tid];
    g_Wqz[(128 + jt)*128 + tid] = s;
    if (tid == 0) {
        float z = 0.f;
        for (int c = 0; c < 128; c++) z += g_Weff[jt*128 + c] * bq[c];
        g_zbias[jt] = z;
    }
}
__global__ void prepW_kernel(const float* __restrict__ Wk, const float* __restrict__ Wv,
                             const float* __restrict__ Wo) {
    int blk = blockIdx.x, tid = threadIdx.x;
    if (blk < 2) {
        fill_chunkR<192>(g_Wqz, 128, blk, 1.f, g_WthQ[blk], g_WtlQ[blk], tid);
    } else {
        int w = (blk - 2) >> 1, kc = (blk - 2) & 1;
        const float* W = (w == 0) ? Wk : (w == 1) ? Wv : Wo;
        fill_chunkR<128>(W, 128, kc, 1.f, g_Wth[w][kc], g_Wtl[w][kc], tid);
    }
}

// ----------------- qproj: N split across 2 blocks (96 each), 2 CTAs/SM (unchanged) --------
__global__ void __launch_bounds__(256,2) qproj_kernel(const float* __restrict__ x,
                                                      const float* __restrict__ bq) {
    extern __shared__ unsigned smw[];
    unsigned *Ah = smw, *Al = smw + TILE_W;
    unsigned sb = (unsigned)__cvta_generic_to_shared(smw);
    unsigned AhB = sb, AlB = sb + TILE_W*4;
    unsigned Bbase = sb + 2*TILE_W*4;
    int tid = threadIdx.x, wid = tid >> 5, lane = tid & 31;
    int g = lane >> 2, tg = lane & 3;
    int nh = blockIdx.x >> 9;
    int q = blockIdx.x & 511;
    int b = q >> 7, h = q & 127;
    const float* src = x + (size_t)b*2097152 + (size_t)h*16384;
    int rowoff = nh*TILH_W;

    prefetch_B2<TILH_W>(g_WthQ[0] + rowoff, g_WtlQ[0] + rowoff,
                        g_WthQ[1] + rowoff, g_WtlQ[1] + rowoff, Bbase, tid);

    float acc[12][4] = {};
    int m0 = (wid >> 1)*32, n0 = (wid & 1)*48;

    fill_chunkR<128>(src, 128, 0, 1.f, Ah, Al, tid);
    cpa_wait0();
    __syncthreads();
    wgemm<2,6>(AhB, AlB, Bbase, Bbase + TILH_W*4, m0, n0, lane, acc);
    __syncthreads();
    fill_chunkR<128>(src, 128, 1, 1.f, Ah, Al, tid);
    __syncthreads();
    wgemm<2,6>(AhB, AlB, Bbase + 2*TILH_W*4, Bbase + 3*TILH_W*4, m0, n0, lane, acc);
    __syncthreads();

    float* stage = (float*)smw;
#pragma unroll
    for (int mt = 0; mt < 2; mt++)
#pragma unroll
        for (int nt = 0; nt < 6; nt++) {
            int m = m0 + mt*16 + g, n = n0 + nt*8 + 2*tg;
            stage[n*132 + m]         = acc[mt*6+nt][0];
            stage[(n+1)*132 + m]     = acc[mt*6+nt][1];
            stage[n*132 + m + 8]     = acc[mt*6+nt][2];
            stage[(n+1)*132 + m + 8] = acc[mt*6+nt][3];
        }
    __syncthreads();

    float* qd = g_q + (size_t)b*2097152 + (size_t)h*128;
    float* zd = g_z + (size_t)b*1048576 + (size_t)h*128;
#pragma unroll
    for (int it = 0; it < 12; it++) {
        int idx = it*256 + tid;
        int ln = idx >> 5, m4 = (idx & 31)*4;
        int gn = nh*96 + ln;
        float4 v = *(float4*)(stage + ln*132 + m4);
        if (gn < 128) {
            float bias = bq[gn];
            v.x += bias; v.y += bias; v.z += bias; v.w += bias;
            *(float4*)(qd + (size_t)gn*16384 + m4) = v;
        } else if (gn < 178) {
            *(float4*)(zd + (size_t)(gn - 128)*16384 + m4) = v;
        }
    }
}

// ----------------- offset2 (unchanged) -----------------
__global__ void __launch_bounds__(256) offset2_kernel() {
    int p = blockIdx.x*256 + threadIdx.x;
    int b = p >> 14, rem = p & 16383;
    int h = rem >> 7, w = rem & 127;
    const float* zb = g_z + (size_t)b*1048576;
    float a0 = g_beff[0], a1 = g_beff[1];
#pragma unroll
    for (int kh = 0; kh < 5; kh++) {
        int hh = h + kh - 2;
        if ((unsigned)hh > 127u) continue;
#pragma unroll
        for (int kw = 0; kw < 5; kw++) {
            int ww = w + kw - 2;
            if ((unsigned)ww > 127u) continue;
            int t = kh*5 + kw, sp = hh*128 + ww;
            a0 += zb[(size_t)t*16384 + sp]        + g_zbias[t];
            a1 += zb[(size_t)(25 + t)*16384 + sp] + g_zbias[25 + t];
        }
    }
    float off0 = tanhf(a0)*5.f, off1 = tanhf(a1)*5.f;
    g_coords[2*p]     = ((float)w + off0)*(128.f/127.f) - 0.5f;
    g_coords[2*p + 1] = ((float)h + off1)*(128.f/127.f) - 0.5f;
}

// ----------------- merged k + vT projection (unchanged) -----------------
__global__ void __launch_bounds__(256,2) pk_kernel(const float* __restrict__ bk,
                                                   const float* __restrict__ bv,
                                                   const float* __restrict__ rel) {
    extern __shared__ unsigned smw[];
    unsigned *Ah = smw, *Al = smw + TILE_W;
    unsigned sb = (unsigned)__cvta_generic_to_shared(smw);
    unsigned AhB = sb, AlB = sb + TILE_W*4;
    unsigned Bbase = sb + 2*TILE_W*4;
    int tid = threadIdx.x, wid = tid >> 5, lane = tid & 31;
    int g = lane >> 2, tg = lane & 3;
    int gb = blockIdx.x;
    int wsel = gb >> 9;
    int q = gb & 511;
    int b = q >> 7, q2 = q & 127;
    int blk_mul = wsel ? 128 : 16384;
    int row_mul = wsel ? 16384 : 128;
    const float* bias = wsel ? bv : bk;
    const float* src = g_xs + (size_t)b*2097152 + (size_t)q2*blk_mul;
    float* dst = wsel ? g_vT : g_k;

    prefetch_B2<TILE_W>(g_Wth[wsel][0], g_Wtl[wsel][0], g_Wth[wsel][1], g_Wtl[wsel][1],
                        Bbase, tid);

    float acc[16][4] = {};
    int m0 = (wid >> 1)*32, n0 = (wid & 1)*64;

    fill_chunkR<128>(src, row_mul, 0, 1.f, Ah, Al, tid);
    cpa_wait0();
    __syncthreads();
    wgemm<2,8>(AhB, AlB, Bbase, Bbase + TILE_W*4, m0, n0, lane, acc);
    __syncthreads();
    fill_chunkR<128>(src, row_mul, 1, 1.f, Ah, Al, tid);
    __syncthreads();
    wgemm<2,8>(AhB, AlB, Bbase + 2*TILE_W*4, Bbase + 3*TILE_W*4, m0, n0, lane, acc);
    __syncthreads();

    float* stage = (float*)smw;
#pragma unroll
    for (int mt = 0; mt < 2; mt++)
#pragma unroll
        for (int nt = 0; nt < 8; nt++) {
            int m = m0 + mt*16 + g, n = n0 + nt*8 + 2*tg;
            stage[n*132 + m]         = acc[mt*8+nt][0];
            stage[(n+1)*132 + m]     = acc[mt*8+nt][1];
            stage[n*132 + m + 8]     = acc[mt*8+nt][2];
            stage[(n+1)*132 + m + 8] = acc[mt*8+nt][3];
        }
    __syncthreads();

    float* db = dst + (size_t)b*2097152 + (size_t)q2*128;
#pragma unroll
    for (int it = 0; it < 16; it++) {
        int idx = it*256 + tid;
        int c = idx >> 5, m4 = (idx & 31)*4;
        float bc = bias[c];
        float4 v = *(float4*)(stage + c*132 + m4);
        if (wsel) {
            float4 rv = *(const float4*)(rel + c*128 + m4);
            v.x += bc + rv.x; v.y += bc + rv.y; v.z += bc + rv.z; v.w += bc + rv.w;
        } else {
            v.x += bc; v.y += bc; v.z += bc; v.w += bc;
        }
        *(float4*)(db + (size_t)c*16384 + m4) = v;
    }
}

// ----------------- bilinear gather (unchanged) -----------------
__global__ void __launch_bounds__(256) sample_kernel(const float* __restrict__ x) {
    int tid = threadIdx.x;
    int lane = tid & 31, wa = tid >> 5;
    int b = blockIdx.x >> 7, h = blockIdx.x & 127;
    const float* xb = x + (size_t)b*2097152;
    for (int w = wa; w < 128; w += 8) {
        size_t p = ((size_t)(b*128 + h))*128 + w;
        float xg = g_coords[2*p], yg = g_coords[2*p + 1];
        float x0 = floorf(xg), y0 = floorf(yg);
        float4 out = make_float4(0.f, 0.f, 0.f, 0.f);
#pragma unroll
        for (int dy = 0; dy < 2; dy++)
#pragma unroll
            for (int dx = 0; dx < 2; dx++) {
                float xi = x0 + (float)dx, yi = y0 + (float)dy;
                float wt = (1.f - fabsf(xg - xi))*(1.f - fabsf(yg - yi));
                bool valid = (xi >= 0.f) && (xi <= 127.f) && (yi >= 0.f) && (yi <= 127.f);
                float wv = valid ? wt : 0.f;
                int ix = min(max((int)xi, 0), 127);
                int iy = min(max((int)yi, 0), 127);
                float4 src = *(const float4*)(xb + ((size_t)(iy*128 + ix))*128 + lane*4);
                out.x += wv*src.x; out.y += wv*src.y; out.z += wv*src.z; out.w += wv*src.w;
            }
        *(float4*)(g_xs + p*128 + lane*4) = out;
    }
}

// ----------------- attention: 4-tile layout, 2 CTAs/SM -----------------
__global__ void __launch_bounds__(256,2) attn_kernel(const float* __restrict__ bo,
                                                     float* __restrict__ out) {
    extern __shared__ unsigned smw[];
    unsigned *Ah = smw, *Al = smw + TILE_W, *Bh = smw + 2*TILE_W, *Bl = smw + 3*TILE_W;
    unsigned sb = (unsigned)__cvta_generic_to_shared(smw);
    unsigned AhB = sb, AlB = sb + TILE_W*4, BhB = sb + 2*TILE_W*4, BlB = sb + 3*TILE_W*4;
    int tid = threadIdx.x, wid = tid >> 5, lane = tid & 31;
    int g = lane >> 2, tg = lane & 3;
    int s = blockIdx.x;
    const float* qs = g_q  + (size_t)s*16384;
    const float* ks = g_k  + (size_t)s*16384;
    const float* vs = g_vT + (size_t)s*16384;
    int m0 = wid*16;

    // ---- S = (q*scale) @ k^T ----
    float sacc[16][4] = {};
    for (int kc = 0; kc < 2; kc++) {
        fill_chunkR<128>(qs, 128, kc, ATT_SCALE, Ah, Al, tid);
        fill_chunkR<128>(ks, 128, kc, 1.f,       Bh, Bl, tid);
        __syncthreads();
        wgemm<1,16>(AhB, AlB, BhB, BlB, m0, 0, lane, sacc);
        __syncthreads();
    }

    // ---- softmax ----
    float mx0 = -1e30f, mx1 = -1e30f;
#pragma unroll
    for (int nt = 0; nt < 16; nt++) {
        mx0 = fmaxf(mx0, fmaxf(sacc[nt][0], sacc[nt][1]));
        mx1 = fmaxf(mx1, fmaxf(sacc[nt][2], sacc[nt][3]));
    }
    mx0 = fmaxf(mx0, __shfl_xor_sync(~0u, mx0, 1)); mx0 = fmaxf(mx0, __shfl_xor_sync(~0u, mx0, 2));
    mx1 = fmaxf(mx1, __shfl_xor_sync(~0u, mx1, 1)); mx1 = fmaxf(mx1, __shfl_xor_sync(~0u, mx1, 2));
    float s0 = 0.f, s1 = 0.f;
#pragma unroll
    for (int nt = 0; nt < 16; nt++) {
        sacc[nt][0] = __expf(sacc[nt][0] - mx0); s0 += sacc[nt][0];
        sacc[nt][1] = __expf(sacc[nt][1] - mx0); s0 += sacc[nt][1];
        sacc[nt][2] = __expf(sacc[nt][2] - mx1); s1 += sacc[nt][2];
        sacc[nt][3] = __expf(sacc[nt][3] - mx1); s1 += sacc[nt][3];
    }
    s0 += __shfl_xor_sync(~0u, s0, 1); s0 += __shfl_xor_sync(~0u, s0, 2);
    s1 += __shfl_xor_sync(~0u, s1, 1); s1 += __shfl_xor_sync(~0u, s1, 2);
    float inv0 = 1.f/s0, inv1 = 1.f/s1;

    // ---- PV = P @ vT^T : P chunk -> A tiles, B = vT chunk ----
    float acc2[16][4] = {};
    for (int kc = 0; kc < 2; kc++) {
#pragma unroll
        for (int nt = 8*kc; nt < 8*kc + 8; nt++) {
            int wcol = (nt - 8*kc)*4 + tg;
            float p0 = sacc[nt][0]*inv0, p1 = sacc[nt][1]*inv0;
            float p2 = sacc[nt][2]*inv1, p3 = sacc[nt][3]*inv1;
            unsigned h0 = packh(p0, p1), h1 = packh(p2, p3);
            int o0 = (m0 + g)*PW + wcol, o1 = (m0 + g + 8)*PW + wcol;
            Ah[o0] = h0; Al[o0] = packl(p0, p1, h0);
            Ah[o1] = h1; Al[o1] = packl(p2, p3, h1);
        }
        fill_chunkR<128>(vs, 128, kc, 1.f, Bh, Bl, tid);
        __syncthreads();
        wgemm<1,16>(AhB, AlB, BhB, BlB, m0, 0, lane, acc2);
        __syncthreads();
    }

    // ---- O = PV @ Wo^T : PV chunk -> A tiles, B = preconverted Wo chunk ----
    float acc3[16][4] = {};
    for (int kc = 0; kc < 2; kc++) {
#pragma unroll
        for (int nt = 8*kc; nt < 8*kc + 8; nt++) {
            int wcol = (nt - 8*kc)*4 + tg;
            float p0 = acc2[nt][0], p1 = acc2[nt][1];
            float p2 = acc2[nt][2], p3 = acc2[nt][3];
            unsigned h0 = packh(p0, p1), h1 = packh(p2, p3);
            int o0 = (m0 + g)*PW + wcol, o1 = (m0 + g + 8)*PW + wcol;
            Ah[o0] = h0; Al[o0] = packl(p0, p1, h0);
            Ah[o1] = h1; Al[o1] = packl(p2, p3, h1);
        }
        copy_tileN<TILE_W>(g_Wth[2][kc], g_Wtl[2][kc], Bh, Bl, tid);
        __syncthreads();
        wgemm<1,16>(AhB, AlB, BhB, BlB, m0, 0, lane, acc3);
        __syncthreads();
    }

    // ---- epilogue ----
    float* ob = out + (size_t)s*16384;
#pragma unroll
    for (int nt = 0; nt < 16; nt++) {
        int n = nt*8 + 2*tg, m = m0 + g;
        float b0 = bo[n], b1 = bo[n+1];
        *(float2*)(ob + (size_t)m*128 + n)     = make_float2(acc3[nt][0] + b0, acc3[nt][1] + b1);
        *(float2*)(ob + (size_t)(m+8)*128 + n) = make_float2(acc3[nt][2] + b0, acc3[nt][3] + b1);
    }
}

// ----------------- launch -----------------
extern "C" void kernel_launch(void* const* d_in, const int* in_sizes, int n_in,
                              void* d_out, int out_size) {
    const float* x   = (const float*)d_in[0];
    const float* Wq  = (const float*)d_in[2];
    const float* bq  = (const float*)d_in[3];
    const float* Wk  = (const float*)d_in[4];
    const float* bk  = (const float*)d_in[5];
    const float* Wv  = (const float*)d_in[6];
    const float* bv  = (const float*)d_in[7];
    const float* Wo  = (const float*)d_in[8];
    const float* bo  = (const float*)d_in[9];
    const float* Wc1 = (const float*)d_in[10];
    const float* bc1 = (const float*)d_in[11];
    const float* Wc2 = (const float*)d_in[12];
    const float* rb  = (const float*)d_in[13];
    float* out = (float*)d_out;

    cudaFuncSetAttribute(qproj_kernel, cudaFuncAttributeMaxDynamicSharedMemorySize, SMEM_Q2);
    cudaFuncSetAttribute(pk_kernel,    cudaFuncAttributeMaxDynamicSharedMemorySize, SMEM_PK);
    cudaFuncSetAttribute(attn_kernel,  cudaFuncAttributeMaxDynamicSharedMemorySize, SMEM_ATT);

    prep_kernel   <<<51,   256>>>(Wq, Wc1, Wc2, bc1);
    prep2_kernel  <<<50,   128>>>(Wq, bq);
    prepW_kernel  <<<8,    256>>>(Wk, Wv, Wo);
    qproj_kernel  <<<1024, 256, SMEM_Q2>>>(x, bq);
    offset2_kernel<<<256,  256>>>();
    sample_kernel <<<512,  256>>>(x);
    pk_kernel     <<<1024, 256, SMEM_PK>>>(bk, bv, rb);
    attn_kernel   <<<512,  256, SMEM_ATT>>>(bo, out);
}